// round 2
// baseline (speedup 1.0000x reference)
#include <cuda_runtime.h>
#include <math.h>

#define BATCH 128
#define SEQ   512
#define INDIM 256
#define HID   1024
#define NCLS  10
#define PSTEP (4 * HID * BATCH)  /* 524288 floats per timestep */

__device__ float g_P[(size_t)SEQ * PSTEP];     // [s][q(4096)][b(128)], q = gate*1024 + dim
__device__ float g_hbuf[2][HID * BATCH];       // [dim][batch]
__device__ float g_cbuf[HID * BATCH];          // [dim][batch]

// ---- packed f32x2 helpers ----
__device__ __forceinline__ double pk2(float x, float y) {
    double r; asm("mov.b64 %0, {%1, %2};" : "=d"(r) : "f"(x), "f"(y)); return r;
}
__device__ __forceinline__ void unpk2(double d, float &x, float &y) {
    asm("mov.b64 {%0, %1}, %2;" : "=f"(x), "=f"(y) : "d"(d));
}
__device__ __forceinline__ double ffma2(double a, double b, double c) {
    double r; asm("fma.rn.f32x2 %0, %1, %2, %3;" : "=d"(r) : "d"(a), "d"(b), "d"(c)); return r;
}
__device__ __forceinline__ float sigf(float x) { return 1.0f / (1.0f + __expf(-x)); }

// ---- init: transpose h0/c0 [b][d] -> [d][b] ----
__global__ void init_kernel(const float* __restrict__ h0, const float* __restrict__ c0) {
    int idx = blockIdx.x * blockDim.x + threadIdx.x;
    int d = idx >> 7, b = idx & 127;
    g_hbuf[0][idx] = h0[b * HID + d];
    g_cbuf[idx]    = c0[b * HID + d];
}

// ---- x projection: P[s][q][b] = W_ih[q,:] . x[b,s,:] + b_ih[q] + b_hh[q] ----
// grid (64 qtiles, 512 s), 256 threads. CTA tile: 64 q x 128 b, K=256.
__global__ __launch_bounds__(256) void xproj_kernel(
        const float* __restrict__ x, const float* __restrict__ W_ih,
        const float* __restrict__ b_ih, const float* __restrict__ b_hh) {
    __shared__ float Xs[32][132];  // [k][b]
    __shared__ float Ws[32][68];   // [k][q]
    int tid = threadIdx.x, lane = tid & 31, w = tid >> 5;
    int qt = blockIdx.x, s = blockIdx.y;
    int q0 = w * 8;               // local q base
    int b0 = lane * 4;

    // x loader: 4 float4 per thread per chunk
    int xb[4], xk[4];
    const float* xp[4];
    #pragma unroll
    for (int it = 0; it < 4; ++it) {
        int f = tid + it * 256;
        xb[it] = f >> 3; xk[it] = (f & 7) * 4;
        xp[it] = x + (size_t)xb[it] * (SEQ * INDIM) + s * INDIM + xk[it];
    }
    // W loader: 2 float4 per thread per chunk
    int wq[2], wk[2];
    const float* wp[2];
    #pragma unroll
    for (int it = 0; it < 2; ++it) {
        int f = tid + it * 256;
        wq[it] = f >> 3; wk[it] = (f & 7) * 4;
        wp[it] = W_ih + (size_t)(qt * 64 + wq[it]) * INDIM + wk[it];
    }

    float4 xR[4], wR[2];
    #pragma unroll
    for (int it = 0; it < 4; ++it) xR[it] = *(const float4*)xp[it];
    #pragma unroll
    for (int it = 0; it < 2; ++it) wR[it] = *(const float4*)wp[it];

    double acc[4][4];  // [qpair][bb]
    #pragma unroll
    for (int p = 0; p < 4; ++p)
        #pragma unroll
        for (int bb = 0; bb < 4; ++bb) acc[p][bb] = 0.0;

    #pragma unroll 1
    for (int c = 0; c < 8; ++c) {
        #pragma unroll
        for (int it = 0; it < 4; ++it) {
            Xs[xk[it]+0][xb[it]] = xR[it].x; Xs[xk[it]+1][xb[it]] = xR[it].y;
            Xs[xk[it]+2][xb[it]] = xR[it].z; Xs[xk[it]+3][xb[it]] = xR[it].w;
        }
        #pragma unroll
        for (int it = 0; it < 2; ++it) {
            Ws[wk[it]+0][wq[it]] = wR[it].x; Ws[wk[it]+1][wq[it]] = wR[it].y;
            Ws[wk[it]+2][wq[it]] = wR[it].z; Ws[wk[it]+3][wq[it]] = wR[it].w;
        }
        __syncthreads();
        if (c < 7) {
            int k0 = (c + 1) * 32;
            #pragma unroll
            for (int it = 0; it < 4; ++it) xR[it] = *(const float4*)(xp[it] + k0);
            #pragma unroll
            for (int it = 0; it < 2; ++it) wR[it] = *(const float4*)(wp[it] + k0);
        }
        #pragma unroll 8
        for (int kk = 0; kk < 32; ++kk) {
            float4 xv = *(const float4*)&Xs[kk][b0];
            double2 w01 = *(const double2*)&Ws[kk][q0];
            double2 w23 = *(const double2*)&Ws[kk][q0 + 4];
            double xb0 = pk2(xv.x, xv.x), xb1 = pk2(xv.y, xv.y);
            double xb2 = pk2(xv.z, xv.z), xb3 = pk2(xv.w, xv.w);
            acc[0][0] = ffma2(w01.x, xb0, acc[0][0]);
            acc[0][1] = ffma2(w01.x, xb1, acc[0][1]);
            acc[0][2] = ffma2(w01.x, xb2, acc[0][2]);
            acc[0][3] = ffma2(w01.x, xb3, acc[0][3]);
            acc[1][0] = ffma2(w01.y, xb0, acc[1][0]);
            acc[1][1] = ffma2(w01.y, xb1, acc[1][1]);
            acc[1][2] = ffma2(w01.y, xb2, acc[1][2]);
            acc[1][3] = ffma2(w01.y, xb3, acc[1][3]);
            acc[2][0] = ffma2(w23.x, xb0, acc[2][0]);
            acc[2][1] = ffma2(w23.x, xb1, acc[2][1]);
            acc[2][2] = ffma2(w23.x, xb2, acc[2][2]);
            acc[2][3] = ffma2(w23.x, xb3, acc[2][3]);
            acc[3][0] = ffma2(w23.y, xb0, acc[3][0]);
            acc[3][1] = ffma2(w23.y, xb1, acc[3][1]);
            acc[3][2] = ffma2(w23.y, xb2, acc[3][2]);
            acc[3][3] = ffma2(w23.y, xb3, acc[3][3]);
        }
        __syncthreads();
    }

    // epilogue: unpack q-pairs into batch-vectors, add bias, store coalesced
    size_t sbase = (size_t)s * PSTEP;
    #pragma unroll
    for (int p = 0; p < 4; ++p) {
        int qlo = qt * 64 + q0 + 2 * p;
        float blo = b_ih[qlo] + b_hh[qlo];
        float bhi = b_ih[qlo + 1] + b_hh[qlo + 1];
        float lo[4], hi[4];
        #pragma unroll
        for (int bb = 0; bb < 4; ++bb) unpk2(acc[p][bb], lo[bb], hi[bb]);
        float4 vlo = make_float4(lo[0] + blo, lo[1] + blo, lo[2] + blo, lo[3] + blo);
        float4 vhi = make_float4(hi[0] + bhi, hi[1] + bhi, hi[2] + bhi, hi[3] + bhi);
        *(float4*)&g_P[sbase + (size_t)qlo * BATCH + b0]       = vlo;
        *(float4*)&g_P[sbase + (size_t)(qlo + 1) * BATCH + b0] = vhi;
    }
}

// ---- one LSTM timestep: CTA j handles dims [j*8, j*8+8), all gates, all batches ----
__global__ __launch_bounds__(256) void step_kernel(int s, const float* __restrict__ W_hh) {
    __shared__ float Hs[32][132];   // [k][b]
    __shared__ float Ws[32][36];    // [k][lq]  (lq = gate*8 + r)
    __shared__ float Gsm[32][132];  // [lq][b]

    const float* __restrict__ h_in = g_hbuf[s & 1];
    float* __restrict__ h_out      = g_hbuf[(s + 1) & 1];
    const float* __restrict__ P    = g_P + (size_t)s * PSTEP;

    int tid = threadIdx.x, lane = tid & 31, w = tid >> 5;
    int j = blockIdx.x;
    int q0 = w * 4;     // local rows q0..q0+3
    int b0 = lane * 4;

    // h loader: 4 float4 per thread per chunk (vector along b)
    int hk[4], hb[4];
    #pragma unroll
    for (int it = 0; it < 4; ++it) {
        int f = tid + it * 256;
        hk[it] = f >> 5; hb[it] = (f & 31) * 4;
    }
    // W loader: 1 float4 per thread per chunk
    int lq = tid >> 3, wk = (tid & 7) * 4;
    int grow = (lq >> 3) * HID + j * 8 + (lq & 7);
    const float* wptr = W_hh + (size_t)grow * HID + wk;

    float4 hR[4], wR;
    #pragma unroll
    for (int it = 0; it < 4; ++it) hR[it] = *(const float4*)&h_in[hk[it] * BATCH + hb[it]];
    wR = *(const float4*)wptr;

    double acc[2][4];  // [qpair][bb]
    #pragma unroll
    for (int p = 0; p < 2; ++p)
        #pragma unroll
        for (int bb = 0; bb < 4; ++bb) acc[p][bb] = 0.0;

    #pragma unroll 1
    for (int c = 0; c < 32; ++c) {
        #pragma unroll
        for (int it = 0; it < 4; ++it) *(float4*)&Hs[hk[it]][hb[it]] = hR[it];
        Ws[wk+0][lq] = wR.x; Ws[wk+1][lq] = wR.y; Ws[wk+2][lq] = wR.z; Ws[wk+3][lq] = wR.w;
        __syncthreads();
        if (c < 31) {
            int k0 = (c + 1) * 32;
            #pragma unroll
            for (int it = 0; it < 4; ++it)
                hR[it] = *(const float4*)&h_in[(k0 + hk[it]) * BATCH + hb[it]];
            wR = *(const float4*)(wptr + k0);
        }
        #pragma unroll 16
        for (int kk = 0; kk < 32; ++kk) {
            float4 hv = *(const float4*)&Hs[kk][b0];
            double2 wv = *(const double2*)&Ws[kk][q0];
            double h0d = pk2(hv.x, hv.x), h1d = pk2(hv.y, hv.y);
            double h2d = pk2(hv.z, hv.z), h3d = pk2(hv.w, hv.w);
            acc[0][0] = ffma2(wv.x, h0d, acc[0][0]);
            acc[0][1] = ffma2(wv.x, h1d, acc[0][1]);
            acc[0][2] = ffma2(wv.x, h2d, acc[0][2]);
            acc[0][3] = ffma2(wv.x, h3d, acc[0][3]);
            acc[1][0] = ffma2(wv.y, h0d, acc[1][0]);
            acc[1][1] = ffma2(wv.y, h1d, acc[1][1]);
            acc[1][2] = ffma2(wv.y, h2d, acc[1][2]);
            acc[1][3] = ffma2(wv.y, h3d, acc[1][3]);
        }
        __syncthreads();
    }

    // epilogue: add P, stage gates in smem
    #pragma unroll
    for (int p = 0; p < 2; ++p) {
        int l0 = q0 + 2 * p, l1 = l0 + 1;
        float lo[4], hi[4];
        #pragma unroll
        for (int bb = 0; bb < 4; ++bb) unpk2(acc[p][bb], lo[bb], hi[bb]);
        int qg0 = (l0 >> 3) * HID + j * 8 + (l0 & 7);
        int qg1 = (l1 >> 3) * HID + j * 8 + (l1 & 7);
        float4 p0 = *(const float4*)&P[(size_t)qg0 * BATCH + b0];
        float4 p1 = *(const float4*)&P[(size_t)qg1 * BATCH + b0];
        float4 v0 = make_float4(lo[0]+p0.x, lo[1]+p0.y, lo[2]+p0.z, lo[3]+p0.w);
        float4 v1 = make_float4(hi[0]+p1.x, hi[1]+p1.y, hi[2]+p1.z, hi[3]+p1.w);
        *(float4*)&Gsm[l0][b0] = v0;
        *(float4*)&Gsm[l1][b0] = v1;
    }
    __syncthreads();

    // LSTM cell: thread -> (r = tid>>5, 4 batches)
    {
        int r = tid >> 5;
        int bc = (tid & 31) * 4;
        float4 gi = *(const float4*)&Gsm[r][bc];
        float4 gf = *(const float4*)&Gsm[8 + r][bc];
        float4 gg = *(const float4*)&Gsm[16 + r][bc];
        float4 go = *(const float4*)&Gsm[24 + r][bc];
        int cidx = (j * 8 + r) * BATCH + bc;
        float4 cv = *(const float4*)&g_cbuf[cidx];
        float* pi = (float*)&gi; float* pf = (float*)&gf;
        float* pg = (float*)&gg; float* po = (float*)&go;
        float* pc = (float*)&cv;
        float4 cn, hn;
        float* pcn = (float*)&cn; float* phn = (float*)&hn;
        #pragma unroll
        for (int e = 0; e < 4; ++e) {
            float iv = sigf(pi[e]);
            float fv = sigf(pf[e]);
            float gv = tanhf(pg[e]);
            float ov = sigf(po[e]);
            float cc = fv * pc[e] + iv * gv;
            pcn[e] = cc;
            phn[e] = ov * tanhf(cc);
        }
        *(float4*)&g_cbuf[cidx] = cn;
        *(float4*)&h_out[cidx]  = hn;
    }
}

// ---- classifier: out[b][c] = W_out[c,:] . h_final[:,b] + b_out[c] ----
__global__ void out_kernel(const float* __restrict__ W_out,
                           const float* __restrict__ b_out,
                           float* __restrict__ out) {
    int c = blockIdx.x, b = blockIdx.y;
    const float* h = g_hbuf[0];  // after 512 steps, final h lands in buffer 0
    float sum = 0.0f;
    for (int d = threadIdx.x; d < HID; d += 128)
        sum += h[d * BATCH + b] * W_out[c * HID + d];
    #pragma unroll
    for (int o = 16; o; o >>= 1) sum += __shfl_xor_sync(0xFFFFFFFFu, sum, o);
    __shared__ float red[4];
    if ((threadIdx.x & 31) == 0) red[threadIdx.x >> 5] = sum;
    __syncthreads();
    if (threadIdx.x == 0)
        out[b * NCLS + c] = red[0] + red[1] + red[2] + red[3] + b_out[c];
}

extern "C" void kernel_launch(void* const* d_in, const int* in_sizes, int n_in,
                              void* d_out, int out_size) {
    const float* x     = (const float*)d_in[0];
    const float* h0    = (const float*)d_in[1];
    const float* c0    = (const float*)d_in[2];
    const float* W_ih  = (const float*)d_in[3];
    const float* W_hh  = (const float*)d_in[4];
    const float* b_ih  = (const float*)d_in[5];
    const float* b_hh  = (const float*)d_in[6];
    const float* W_out = (const float*)d_in[7];
    const float* b_out = (const float*)d_in[8];
    float* out = (float*)d_out;

    init_kernel<<<HID * BATCH / 256, 256>>>(h0, c0);
    xproj_kernel<<<dim3(64, SEQ), 256>>>(x, W_ih, b_ih, b_hh);
    for (int s = 0; s < SEQ; ++s)
        step_kernel<<<128, 256>>>(s, W_hh);
    out_kernel<<<dim3(NCLS, BATCH), 128>>>(W_out, b_out, out);
}

// round 4
// speedup vs baseline: 1.2889x; 1.2889x over previous
#include <cuda_runtime.h>
#include <cuda_bf16.h>
#include <cstdint>
#include <math.h>

#define BATCH 128
#define SEQ   512
#define INDIM 256
#define HID   1024
#define NCLS  10
#define PSTEP (4 * HID * BATCH)

// ---------------- device globals ----------------
__device__ float g_P[(size_t)SEQ * PSTEP];   // [s][q(4096)][b(128)], q = gate*1024 + d
// W split, rows permuted: ct = d>>3, r = gate*8 + (d&7); stored [ct*32 + r][k]
__device__ __align__(16) __nv_bfloat16 g_Whi[4096 * 1024];
__device__ __align__(16) __nv_bfloat16 g_Wlo[4096 * 1024];
__device__ __align__(16) __nv_bfloat16 g_hhi[2][BATCH * HID];   // [b][d]
__device__ __align__(16) __nv_bfloat16 g_hlo[2][BATCH * HID];   // [b][d]
__device__ float g_c[HID * BATCH];                              // [d][b]

__device__ __forceinline__ uint32_t smem_u32(const void* p) {
    uint32_t a;
    asm("{ .reg .u64 t; cvta.to.shared.u64 t, %1; cvt.u32.u64 %0, t; }" : "=r"(a) : "l"(p));
    return a;
}
__device__ __forceinline__ void cp16(uint32_t dst, const void* src) {
    asm volatile("cp.async.cg.shared.global [%0], [%1], 16;" :: "r"(dst), "l"(src));
}
#define CP_COMMIT() asm volatile("cp.async.commit_group;" ::: "memory")
#define CP_WAIT(n)  asm volatile("cp.async.wait_group %0;" :: "n"(n) : "memory")

__device__ __forceinline__ void mma16816(float* c, uint32_t a0, uint32_t a1,
                                         uint32_t a2, uint32_t a3,
                                         uint32_t b0, uint32_t b1) {
    asm volatile(
        "mma.sync.aligned.m16n8k16.row.col.f32.bf16.bf16.f32 "
        "{%0,%1,%2,%3}, {%4,%5,%6,%7}, {%8,%9}, {%0,%1,%2,%3};"
        : "+f"(c[0]), "+f"(c[1]), "+f"(c[2]), "+f"(c[3])
        : "r"(a0), "r"(a1), "r"(a2), "r"(a3), "r"(b0), "r"(b1));
}
__device__ __forceinline__ float sigf(float x) { return 1.0f / (1.0f + __expf(-x)); }

// ---------------- init: W split + row permutation ----------------
__global__ void splitW_kernel(const float* __restrict__ W_hh) {
    int k = blockIdx.y * 256 + threadIdx.x;
    int q = blockIdx.x;                       // 0..4095 (gate*1024 + d)
    int gate = q >> 10, d = q & 1023;
    int ct = d >> 3, jd = d & 7;
    size_t dst = ((size_t)ct * 32 + gate * 8 + jd) * 1024 + k;
    float w = W_hh[(size_t)q * 1024 + k];
    __nv_bfloat16 hi = __float2bfloat16(w);
    g_Whi[dst] = hi;
    g_Wlo[dst] = __float2bfloat16(w - __bfloat162float(hi));
}

__global__ void init_state(const float* __restrict__ h0, const float* __restrict__ c0) {
    int idx = blockIdx.x * 256 + threadIdx.x;   // over [b][d]
    int b = idx >> 10, d = idx & 1023;
    float h = h0[idx];
    __nv_bfloat16 hi = __float2bfloat16(h);
    g_hhi[0][idx] = hi;
    g_hlo[0][idx] = __float2bfloat16(h - __bfloat162float(hi));
    g_c[(size_t)d * 128 + b] = c0[idx];
}

// ---------------- x projection (FFMA2, unchanged from passing R2) ----------------
__device__ __forceinline__ double pk2(float x, float y) {
    double r; asm("mov.b64 %0, {%1, %2};" : "=d"(r) : "f"(x), "f"(y)); return r;
}
__device__ __forceinline__ void unpk2(double d, float &x, float &y) {
    asm("mov.b64 {%0, %1}, %2;" : "=f"(x), "=f"(y) : "d"(d));
}
__device__ __forceinline__ double ffma2(double a, double b, double c) {
    double r; asm("fma.rn.f32x2 %0, %1, %2, %3;" : "=d"(r) : "d"(a), "d"(b), "d"(c)); return r;
}

__global__ __launch_bounds__(256) void xproj_kernel(
        const float* __restrict__ x, const float* __restrict__ W_ih,
        const float* __restrict__ b_ih, const float* __restrict__ b_hh) {
    __shared__ float Xs[32][132];
    __shared__ float Ws[32][68];
    int tid = threadIdx.x, lane = tid & 31, w = tid >> 5;
    int qt = blockIdx.x, s = blockIdx.y;
    int q0 = w * 8, b0 = lane * 4;

    int xb[4], xk[4]; const float* xp[4];
    #pragma unroll
    for (int it = 0; it < 4; ++it) {
        int f = tid + it * 256;
        xb[it] = f >> 3; xk[it] = (f & 7) * 4;
        xp[it] = x + (size_t)xb[it] * (SEQ * INDIM) + s * INDIM + xk[it];
    }
    int wq[2], wk[2]; const float* wp[2];
    #pragma unroll
    for (int it = 0; it < 2; ++it) {
        int f = tid + it * 256;
        wq[it] = f >> 3; wk[it] = (f & 7) * 4;
        wp[it] = W_ih + (size_t)(qt * 64 + wq[it]) * INDIM + wk[it];
    }
    float4 xR[4], wR[2];
    #pragma unroll
    for (int it = 0; it < 4; ++it) xR[it] = *(const float4*)xp[it];
    #pragma unroll
    for (int it = 0; it < 2; ++it) wR[it] = *(const float4*)wp[it];

    double acc[4][4];
    #pragma unroll
    for (int p = 0; p < 4; ++p)
        #pragma unroll
        for (int bb = 0; bb < 4; ++bb) acc[p][bb] = 0.0;

    #pragma unroll 1
    for (int c = 0; c < 8; ++c) {
        #pragma unroll
        for (int it = 0; it < 4; ++it) {
            Xs[xk[it]+0][xb[it]] = xR[it].x; Xs[xk[it]+1][xb[it]] = xR[it].y;
            Xs[xk[it]+2][xb[it]] = xR[it].z; Xs[xk[it]+3][xb[it]] = xR[it].w;
        }
        #pragma unroll
        for (int it = 0; it < 2; ++it) {
            Ws[wk[it]+0][wq[it]] = wR[it].x; Ws[wk[it]+1][wq[it]] = wR[it].y;
            Ws[wk[it]+2][wq[it]] = wR[it].z; Ws[wk[it]+3][wq[it]] = wR[it].w;
        }
        __syncthreads();
        if (c < 7) {
            int k0 = (c + 1) * 32;
            #pragma unroll
            for (int it = 0; it < 4; ++it) xR[it] = *(const float4*)(xp[it] + k0);
            #pragma unroll
            for (int it = 0; it < 2; ++it) wR[it] = *(const float4*)(wp[it] + k0);
        }
        #pragma unroll 8
        for (int kk = 0; kk < 32; ++kk) {
            float4 xv = *(const float4*)&Xs[kk][b0];
            double2 w01 = *(const double2*)&Ws[kk][q0];
            double2 w23 = *(const double2*)&Ws[kk][q0 + 4];
            double xb0 = pk2(xv.x, xv.x), xb1 = pk2(xv.y, xv.y);
            double xb2 = pk2(xv.z, xv.z), xb3 = pk2(xv.w, xv.w);
            acc[0][0] = ffma2(w01.x, xb0, acc[0][0]);
            acc[0][1] = ffma2(w01.x, xb1, acc[0][1]);
            acc[0][2] = ffma2(w01.x, xb2, acc[0][2]);
            acc[0][3] = ffma2(w01.x, xb3, acc[0][3]);
            acc[1][0] = ffma2(w01.y, xb0, acc[1][0]);
            acc[1][1] = ffma2(w01.y, xb1, acc[1][1]);
            acc[1][2] = ffma2(w01.y, xb2, acc[1][2]);
            acc[1][3] = ffma2(w01.y, xb3, acc[1][3]);
            acc[2][0] = ffma2(w23.x, xb0, acc[2][0]);
            acc[2][1] = ffma2(w23.x, xb1, acc[2][1]);
            acc[2][2] = ffma2(w23.x, xb2, acc[2][2]);
            acc[2][3] = ffma2(w23.x, xb3, acc[2][3]);
            acc[3][0] = ffma2(w23.y, xb0, acc[3][0]);
            acc[3][1] = ffma2(w23.y, xb1, acc[3][1]);
            acc[3][2] = ffma2(w23.y, xb2, acc[3][2]);
            acc[3][3] = ffma2(w23.y, xb3, acc[3][3]);
        }
        __syncthreads();
    }
    size_t sbase = (size_t)s * PSTEP;
    #pragma unroll
    for (int p = 0; p < 4; ++p) {
        int qlo = qt * 64 + q0 + 2 * p;
        float blo = b_ih[qlo] + b_hh[qlo];
        float bhi = b_ih[qlo + 1] + b_hh[qlo + 1];
        float lo[4], hi[4];
        #pragma unroll
        for (int bb = 0; bb < 4; ++bb) unpk2(acc[p][bb], lo[bb], hi[bb]);
        float4 vlo = make_float4(lo[0] + blo, lo[1] + blo, lo[2] + blo, lo[3] + blo);
        float4 vhi = make_float4(hi[0] + bhi, hi[1] + bhi, hi[2] + bhi, hi[3] + bhi);
        *(float4*)&g_P[sbase + (size_t)qlo * BATCH + b0]       = vlo;
        *(float4*)&g_P[sbase + (size_t)(qlo + 1) * BATCH + b0] = vhi;
    }
}

// ---------------- mma.sync LSTM step ----------------
// 128 CTAs x 128 thr. CTA ct: rows = 4 gates x dims [ct*8, ct*8+8), all 128 batches.
// D[32,128] = sum over 48 chunks (3 passes x 16) of A[32,64] * B[128,64]^T.
#define KCH    64
#define PIT    72                       /* bf16 pitch per row (64 + 8 pad) */
#define A_SZ   (32 * PIT * 2)           /* 4608  */
#define B_SZ   (128 * PIT * 2)          /* 18432 */
#define STG    (A_SZ + B_SZ)            /* 23040 */
#define NCHUNK 48
#define STEP_SMEM (3 * STG)             /* 69120 */

__global__ __launch_bounds__(128, 1) void step_mma(int s) {
    extern __shared__ char smem[];
    uint32_t sb = smem_u32(smem);
    int tid = threadIdx.x, lane = tid & 31, wid = tid >> 5;
    int g = lane >> 2, tc = lane & 3;
    int ct = blockIdx.x;

    const __nv_bfloat16* hhi_in = g_hhi[s & 1];
    const __nv_bfloat16* hlo_in = g_hlo[s & 1];
    __nv_bfloat16* hhi_out = g_hhi[(s + 1) & 1];
    __nv_bfloat16* hlo_out = g_hlo[(s + 1) & 1];
    const float* P = g_P + (size_t)s * PSTEP;

    const __nv_bfloat16* Ahi = g_Whi + (size_t)ct * 32 * 1024;
    const __nv_bfloat16* Alo = g_Wlo + (size_t)ct * 32 * 1024;

    // per-thread loader coords
    int ar[2], ac[2], br[8], bc[8];
    #pragma unroll
    for (int i = 0; i < 2; ++i) { int u = tid + i * 128; ar[i] = u >> 3; ac[i] = u & 7; }
    #pragma unroll
    for (int i = 0; i < 8; ++i) { int u = tid + i * 128; br[i] = u >> 3; bc[i] = u & 7; }

    auto issue = [&](int chunk, int st) {
        int pass = chunk >> 4, kc = chunk & 15;
        const __nv_bfloat16* Ab = (pass == 1) ? Alo : Ahi;
        const __nv_bfloat16* Bb = (pass == 2) ? hlo_in : hhi_in;
        int k0 = kc * KCH;
        uint32_t sA = sb + st * STG;
        uint32_t sB = sA + A_SZ;
        #pragma unroll
        for (int i = 0; i < 2; ++i)
            cp16(sA + ar[i] * (PIT * 2) + ac[i] * 16, Ab + ar[i] * 1024 + k0 + ac[i] * 8);
        #pragma unroll
        for (int i = 0; i < 8; ++i)
            cp16(sB + br[i] * (PIT * 2) + bc[i] * 16, Bb + (size_t)br[i] * 1024 + k0 + bc[i] * 8);
        CP_COMMIT();
    };

    float acc[2][4][4];
    #pragma unroll
    for (int m = 0; m < 2; ++m)
        #pragma unroll
        for (int n = 0; n < 4; ++n)
            #pragma unroll
            for (int e = 0; e < 4; ++e) acc[m][n][e] = 0.0f;

    issue(0, 0);
    issue(1, 1);

    int n0 = wid * 32;
    #pragma unroll 1
    for (int c = 0; c < NCHUNK; ++c) {
        if (c < NCHUNK - 1) CP_WAIT(1); else CP_WAIT(0);
        __syncthreads();
        if (c + 2 < NCHUNK) issue(c + 2, (c + 2) % 3);
        const __nv_bfloat16* sA = (const __nv_bfloat16*)(smem + (c % 3) * STG);
        const __nv_bfloat16* sB = (const __nv_bfloat16*)(smem + (c % 3) * STG + A_SZ);
        #pragma unroll
        for (int ks = 0; ks < 4; ++ks) {
            int kb = ks * 16;
            uint32_t a[2][4];
            #pragma unroll
            for (int m = 0; m < 2; ++m) {
                int m0 = m * 16;
                a[m][0] = *(const uint32_t*)&sA[(m0 + g) * PIT + kb + 2 * tc];
                a[m][1] = *(const uint32_t*)&sA[(m0 + g + 8) * PIT + kb + 2 * tc];
                a[m][2] = *(const uint32_t*)&sA[(m0 + g) * PIT + kb + 2 * tc + 8];
                a[m][3] = *(const uint32_t*)&sA[(m0 + g + 8) * PIT + kb + 2 * tc + 8];
            }
            #pragma unroll
            for (int n = 0; n < 4; ++n) {
                int nn = n0 + n * 8 + g;
                uint32_t b0 = *(const uint32_t*)&sB[nn * PIT + kb + 2 * tc];
                uint32_t b1 = *(const uint32_t*)&sB[nn * PIT + kb + 2 * tc + 8];
                mma16816(acc[0][n], a[0][0], a[0][1], a[0][2], a[0][3], b0, b1);
                mma16816(acc[1][n], a[1][0], a[1][1], a[1][2], a[1][3], b0, b1);
            }
        }
    }

    // ---- epilogue: frags -> Gsm ----
    __syncthreads();
    float* Gsm = (float*)smem;          // [32][132]
    #pragma unroll
    for (int m = 0; m < 2; ++m) {
        #pragma unroll
        for (int n = 0; n < 4; ++n) {
            int row0 = m * 16 + g, col = n0 + n * 8 + 2 * tc;
            *(float2*)&Gsm[row0 * 132 + col]       = make_float2(acc[m][n][0], acc[m][n][1]);
            *(float2*)&Gsm[(row0 + 8) * 132 + col] = make_float2(acc[m][n][2], acc[m][n][3]);
        }
    }
    __syncthreads();

    // ---- LSTM cell: thread -> (dim jd, 8 batches) ----
    {
        int jd = tid >> 4;              // 0..7
        int bq = (tid & 15) * 8;        // batch base
        int d = ct * 8 + jd;
        #pragma unroll
        for (int half = 0; half < 2; ++half) {
            int b = bq + half * 4;
            float4 gi = *(const float4*)&Gsm[(0 * 8 + jd) * 132 + b];
            float4 gf = *(const float4*)&Gsm[(1 * 8 + jd) * 132 + b];
            float4 gg = *(const float4*)&Gsm[(2 * 8 + jd) * 132 + b];
            float4 go = *(const float4*)&Gsm[(3 * 8 + jd) * 132 + b];
            float4 pi = *(const float4*)&P[((size_t)(0 * 1024 + d)) * 128 + b];
            float4 pf = *(const float4*)&P[((size_t)(1 * 1024 + d)) * 128 + b];
            float4 pg = *(const float4*)&P[((size_t)(2 * 1024 + d)) * 128 + b];
            float4 po = *(const float4*)&P[((size_t)(3 * 1024 + d)) * 128 + b];
            float4 cv = *(const float4*)&g_c[(size_t)d * 128 + b];
            float4 cn;
            #pragma unroll
            for (int e = 0; e < 4; ++e) {
                float zi = ((const float*)&gi)[e] + ((const float*)&pi)[e];
                float zf = ((const float*)&gf)[e] + ((const float*)&pf)[e];
                float zg = ((const float*)&gg)[e] + ((const float*)&pg)[e];
                float zo = ((const float*)&go)[e] + ((const float*)&po)[e];
                float iv = sigf(zi), fv = sigf(zf), gv = tanhf(zg), ov = sigf(zo);
                float cc = fv * ((const float*)&cv)[e] + iv * gv;
                ((float*)&cn)[e] = cc;
                float hv = ov * tanhf(cc);
                __nv_bfloat16 hb = __float2bfloat16(hv);
                hhi_out[(size_t)(b + e) * 1024 + d] = hb;
                hlo_out[(size_t)(b + e) * 1024 + d] =
                    __float2bfloat16(hv - __bfloat162float(hb));
            }
            *(float4*)&g_c[(size_t)d * 128 + b] = cn;
        }
    }
}

// ---------------- classifier ----------------
__global__ void out_kernel(const float* __restrict__ W_out,
                           const float* __restrict__ b_out,
                           float* __restrict__ out) {
    int c = blockIdx.x, b = blockIdx.y;
    const __nv_bfloat16* hh = g_hhi[0] + (size_t)b * HID;
    const __nv_bfloat16* hl = g_hlo[0] + (size_t)b * HID;
    float sum = 0.0f;
    for (int d = threadIdx.x; d < HID; d += 128)
        sum += (__bfloat162float(hh[d]) + __bfloat162float(hl[d])) * W_out[c * HID + d];
    #pragma unroll
    for (int o = 16; o; o >>= 1) sum += __shfl_xor_sync(0xFFFFFFFFu, sum, o);
    __shared__ float red[4];
    if ((threadIdx.x & 31) == 0) red[threadIdx.x >> 5] = sum;
    __syncthreads();
    if (threadIdx.x == 0)
        out[b * NCLS + c] = red[0] + red[1] + red[2] + red[3] + b_out[c];
}

extern "C" void kernel_launch(void* const* d_in, const int* in_sizes, int n_in,
                              void* d_out, int out_size) {
    const float* x     = (const float*)d_in[0];
    const float* h0    = (const float*)d_in[1];
    const float* c0    = (const float*)d_in[2];
    const float* W_ih  = (const float*)d_in[3];
    const float* W_hh  = (const float*)d_in[4];
    const float* b_ih  = (const float*)d_in[5];
    const float* b_hh  = (const float*)d_in[6];
    const float* W_out = (const float*)d_in[7];
    const float* b_out = (const float*)d_in[8];
    float* out = (float*)d_out;

    cudaFuncSetAttribute(step_mma, cudaFuncAttributeMaxDynamicSharedMemorySize, STEP_SMEM);

    init_state<<<BATCH * HID / 256, 256>>>(h0, c0);
    splitW_kernel<<<dim3(4096, 4), 256>>>(W_hh);
    xproj_kernel<<<dim3(64, SEQ), 256>>>(x, W_ih, b_ih, b_hh);
    for (int s = 0; s < SEQ; ++s)
        step_mma<<<128, 128, STEP_SMEM>>>(s);
    out_kernel<<<dim3(NCLS, BATCH), 128>>>(W_out, b_out, out);
}

// round 5
// speedup vs baseline: 1.5906x; 1.2340x over previous
#include <cuda_runtime.h>
#include <cuda_bf16.h>
#include <cstdint>
#include <math.h>

#define BATCH 128
#define SEQ   512
#define INDIM 256
#define HID   1024
#define NCLS  10
#define PSTEP (4 * HID * BATCH)

// ---------------- device globals ----------------
__device__ float g_P[(size_t)SEQ * PSTEP];   // [s][q(4096)][b(128)], q = gate*1024 + d
__device__ __align__(16) __nv_bfloat16 g_hhi[2][BATCH * HID];   // [b][d]
__device__ __align__(16) __nv_bfloat16 g_hlo[2][BATCH * HID];   // [b][d]
__device__ unsigned g_bar;

__device__ __forceinline__ uint32_t smem_u32(const void* p) {
    uint32_t a;
    asm("{ .reg .u64 t; cvta.to.shared.u64 t, %1; cvt.u32.u64 %0, t; }" : "=r"(a) : "l"(p));
    return a;
}
__device__ __forceinline__ void cp16(uint32_t dst, const void* src) {
    asm volatile("cp.async.cg.shared.global [%0], [%1], 16;" :: "r"(dst), "l"(src));
}
#define CP_COMMIT() asm volatile("cp.async.commit_group;" ::: "memory")
#define CP_WAIT(n)  asm volatile("cp.async.wait_group %0;" :: "n"(n) : "memory")

__device__ __forceinline__ void mma16816(float* c, uint32_t a0, uint32_t a1,
                                         uint32_t a2, uint32_t a3,
                                         uint32_t b0, uint32_t b1) {
    asm volatile(
        "mma.sync.aligned.m16n8k16.row.col.f32.bf16.bf16.f32 "
        "{%0,%1,%2,%3}, {%4,%5,%6,%7}, {%8,%9}, {%0,%1,%2,%3};"
        : "+f"(c[0]), "+f"(c[1]), "+f"(c[2]), "+f"(c[3])
        : "r"(a0), "r"(a1), "r"(a2), "r"(a3), "r"(b0), "r"(b1));
}
__device__ __forceinline__ float sigf(float x) { return 1.0f / (1.0f + __expf(-x)); }

// ---------------- init: state + barrier reset ----------------
__global__ void init_state(const float* __restrict__ h0) {
    int idx = blockIdx.x * 256 + threadIdx.x;   // over [b][d]
    if (idx == 0) g_bar = 0;
    float h = h0[idx];
    __nv_bfloat16 hi = __float2bfloat16(h);
    g_hhi[0][idx] = hi;
    g_hlo[0][idx] = __float2bfloat16(h - __bfloat162float(hi));
}

// ---------------- x projection (FFMA2, proven) ----------------
__device__ __forceinline__ double pk2(float x, float y) {
    double r; asm("mov.b64 %0, {%1, %2};" : "=d"(r) : "f"(x), "f"(y)); return r;
}
__device__ __forceinline__ void unpk2(double d, float &x, float &y) {
    asm("mov.b64 {%0, %1}, %2;" : "=f"(x), "=f"(y) : "d"(d));
}
__device__ __forceinline__ double ffma2(double a, double b, double c) {
    double r; asm("fma.rn.f32x2 %0, %1, %2, %3;" : "=d"(r) : "d"(a), "d"(b), "d"(c)); return r;
}

__global__ __launch_bounds__(256) void xproj_kernel(
        const float* __restrict__ x, const float* __restrict__ W_ih,
        const float* __restrict__ b_ih, const float* __restrict__ b_hh) {
    __shared__ float Xs[32][132];
    __shared__ float Ws[32][68];
    int tid = threadIdx.x, lane = tid & 31, w = tid >> 5;
    int qt = blockIdx.x, s = blockIdx.y;
    int q0 = w * 8, b0 = lane * 4;

    int xb[4], xk[4]; const float* xp[4];
    #pragma unroll
    for (int it = 0; it < 4; ++it) {
        int f = tid + it * 256;
        xb[it] = f >> 3; xk[it] = (f & 7) * 4;
        xp[it] = x + (size_t)xb[it] * (SEQ * INDIM) + s * INDIM + xk[it];
    }
    int wq[2], wk[2]; const float* wp[2];
    #pragma unroll
    for (int it = 0; it < 2; ++it) {
        int f = tid + it * 256;
        wq[it] = f >> 3; wk[it] = (f & 7) * 4;
        wp[it] = W_ih + (size_t)(qt * 64 + wq[it]) * INDIM + wk[it];
    }
    float4 xR[4], wR[2];
    #pragma unroll
    for (int it = 0; it < 4; ++it) xR[it] = *(const float4*)xp[it];
    #pragma unroll
    for (int it = 0; it < 2; ++it) wR[it] = *(const float4*)wp[it];

    double acc[4][4];
    #pragma unroll
    for (int p = 0; p < 4; ++p)
        #pragma unroll
        for (int bb = 0; bb < 4; ++bb) acc[p][bb] = 0.0;

    #pragma unroll 1
    for (int c = 0; c < 8; ++c) {
        #pragma unroll
        for (int it = 0; it < 4; ++it) {
            Xs[xk[it]+0][xb[it]] = xR[it].x; Xs[xk[it]+1][xb[it]] = xR[it].y;
            Xs[xk[it]+2][xb[it]] = xR[it].z; Xs[xk[it]+3][xb[it]] = xR[it].w;
        }
        #pragma unroll
        for (int it = 0; it < 2; ++it) {
            Ws[wk[it]+0][wq[it]] = wR[it].x; Ws[wk[it]+1][wq[it]] = wR[it].y;
            Ws[wk[it]+2][wq[it]] = wR[it].z; Ws[wk[it]+3][wq[it]] = wR[it].w;
        }
        __syncthreads();
        if (c < 7) {
            int k0 = (c + 1) * 32;
            #pragma unroll
            for (int it = 0; it < 4; ++it) xR[it] = *(const float4*)(xp[it] + k0);
            #pragma unroll
            for (int it = 0; it < 2; ++it) wR[it] = *(const float4*)(wp[it] + k0);
        }
        #pragma unroll 8
        for (int kk = 0; kk < 32; ++kk) {
            float4 xv = *(const float4*)&Xs[kk][b0];
            double2 w01 = *(const double2*)&Ws[kk][q0];
            double2 w23 = *(const double2*)&Ws[kk][q0 + 4];
            double xb0 = pk2(xv.x, xv.x), xb1 = pk2(xv.y, xv.y);
            double xb2 = pk2(xv.z, xv.z), xb3 = pk2(xv.w, xv.w);
            acc[0][0] = ffma2(w01.x, xb0, acc[0][0]);
            acc[0][1] = ffma2(w01.x, xb1, acc[0][1]);
            acc[0][2] = ffma2(w01.x, xb2, acc[0][2]);
            acc[0][3] = ffma2(w01.x, xb3, acc[0][3]);
            acc[1][0] = ffma2(w01.y, xb0, acc[1][0]);
            acc[1][1] = ffma2(w01.y, xb1, acc[1][1]);
            acc[1][2] = ffma2(w01.y, xb2, acc[1][2]);
            acc[1][3] = ffma2(w01.y, xb3, acc[1][3]);
            acc[2][0] = ffma2(w23.x, xb0, acc[2][0]);
            acc[2][1] = ffma2(w23.x, xb1, acc[2][1]);
            acc[2][2] = ffma2(w23.x, xb2, acc[2][2]);
            acc[2][3] = ffma2(w23.x, xb3, acc[2][3]);
            acc[3][0] = ffma2(w23.y, xb0, acc[3][0]);
            acc[3][1] = ffma2(w23.y, xb1, acc[3][1]);
            acc[3][2] = ffma2(w23.y, xb2, acc[3][2]);
            acc[3][3] = ffma2(w23.y, xb3, acc[3][3]);
        }
        __syncthreads();
    }
    size_t sbase = (size_t)s * PSTEP;
    #pragma unroll
    for (int p = 0; p < 4; ++p) {
        int qlo = qt * 64 + q0 + 2 * p;
        float blo = b_ih[qlo] + b_hh[qlo];
        float bhi = b_ih[qlo + 1] + b_hh[qlo + 1];
        float lo[4], hi[4];
        #pragma unroll
        for (int bb = 0; bb < 4; ++bb) unpk2(acc[p][bb], lo[bb], hi[bb]);
        float4 vlo = make_float4(lo[0] + blo, lo[1] + blo, lo[2] + blo, lo[3] + blo);
        float4 vhi = make_float4(hi[0] + bhi, hi[1] + bhi, hi[2] + bhi, hi[3] + bhi);
        *(float4*)&g_P[sbase + (size_t)qlo * BATCH + b0]       = vlo;
        *(float4*)&g_P[sbase + (size_t)(qlo + 1) * BATCH + b0] = vhi;
    }
}

// ---------------- persistent LSTM recurrence ----------------
// 128 CTAs x 256 thr, 1 CTA/SM. CTA ct owns rows = 4 gates x dims [ct*8,ct*8+8).
// A (Whi/Wlo, 32x1024) resident in smem; c-state in registers; per step stream
// h chunks (hhi used by Ahi+Alo sets, hlo by Ahi), global barrier between steps.
#define PIT_A 1032
#define PIT_B 72
#define B_STG 18432
#define SM_A_HI 0
#define SM_A_LO 66048
#define SM_P    132096
#define SM_B    148480
#define SM_G    SM_B
#define STEP_SMEM (SM_B + 3 * B_STG)   /* 203776 */

__global__ __launch_bounds__(256, 1) void step_persist(
        const float* __restrict__ W_hh, const float* __restrict__ c0) {
    extern __shared__ char smem[];
    uint32_t sb = smem_u32(smem);
    int tid = threadIdx.x, lane = tid & 31, wid = tid >> 5;
    int g = lane >> 2, tc = lane & 3;
    int ct = blockIdx.x;
    int nh = wid & 1, kq = wid >> 1;       // n-half, k-quarter
    int n0 = nh * 64;

    __nv_bfloat16* sAhi = (__nv_bfloat16*)(smem + SM_A_HI);   // [32][1032]
    __nv_bfloat16* sAlo = (__nv_bfloat16*)(smem + SM_A_LO);
    float* Psm = (float*)(smem + SM_P);                        // [32][128]
    float* Gsm = (float*)(smem + SM_G);                        // [32][132]

    // ---- load + split A once ----
    {
        int lr = tid >> 3, seg = tid & 7;
        int gate = lr >> 3, jd = lr & 7;
        const float* src = W_hh + (size_t)(gate * HID + ct * 8 + jd) * HID + seg * 128;
        #pragma unroll 4
        for (int i = 0; i < 32; ++i) {
            float4 v = *(const float4*)(src + i * 4);
            int k = seg * 128 + i * 4;
            __nv_bfloat16 h0 = __float2bfloat16(v.x);
            __nv_bfloat16 h1 = __float2bfloat16(v.y);
            __nv_bfloat16 h2 = __float2bfloat16(v.z);
            __nv_bfloat16 h3 = __float2bfloat16(v.w);
            sAhi[lr * PIT_A + k + 0] = h0;
            sAhi[lr * PIT_A + k + 1] = h1;
            sAhi[lr * PIT_A + k + 2] = h2;
            sAhi[lr * PIT_A + k + 3] = h3;
            sAlo[lr * PIT_A + k + 0] = __float2bfloat16(v.x - __bfloat162float(h0));
            sAlo[lr * PIT_A + k + 1] = __float2bfloat16(v.y - __bfloat162float(h1));
            sAlo[lr * PIT_A + k + 2] = __float2bfloat16(v.z - __bfloat162float(h2));
            sAlo[lr * PIT_A + k + 3] = __float2bfloat16(v.w - __bfloat162float(h3));
        }
    }

    // ---- c-state in registers ----
    int cb = tid & 127, cdg = tid >> 7;    // batch, dim-group(4)
    float creg[4];
    {
        float4 cv = *(const float4*)&c0[(size_t)cb * HID + ct * 8 + cdg * 4];
        creg[0] = cv.x; creg[1] = cv.y; creg[2] = cv.z; creg[3] = cv.w;
    }
    __syncthreads();

    // B loader coords
    int brow[4], bseg[4];
    #pragma unroll
    for (int i = 0; i < 4; ++i) { int u = tid + i * 256; brow[i] = u >> 3; bseg[i] = u & 7; }
    // P loader coords
    int pq[4], ps[4];
    #pragma unroll
    for (int i = 0; i < 4; ++i) { int u = tid + i * 256; pq[i] = u >> 5; ps[i] = u & 31; }

    #pragma unroll 1
    for (int s = 0; s < SEQ; ++s) {
        const __nv_bfloat16* hhi_in = g_hhi[s & 1];
        const __nv_bfloat16* hlo_in = g_hlo[s & 1];
        __nv_bfloat16* hhi_out = g_hhi[(s + 1) & 1];
        __nv_bfloat16* hlo_out = g_hlo[(s + 1) & 1];
        const float* Pg = g_P + (size_t)s * PSTEP;

        // issue P + B chunk0 (one group), then chunk1
        #pragma unroll
        for (int i = 0; i < 4; ++i) {
            int qg = (pq[i] >> 3) * HID + ct * 8 + (pq[i] & 7);
            cp16(sb + SM_P + pq[i] * 512 + ps[i] * 16, Pg + (size_t)qg * BATCH + ps[i] * 4);
        }
        #pragma unroll
        for (int i = 0; i < 4; ++i)
            cp16(sb + SM_B + brow[i] * (PIT_B * 2) + bseg[i] * 16,
                 hhi_in + (size_t)brow[i] * HID + bseg[i] * 8);
        CP_COMMIT();
        #pragma unroll
        for (int i = 0; i < 4; ++i)
            cp16(sb + SM_B + B_STG + brow[i] * (PIT_B * 2) + bseg[i] * 16,
                 hhi_in + (size_t)brow[i] * HID + 64 + bseg[i] * 8);
        CP_COMMIT();

        float acc[2][8][4];
        #pragma unroll
        for (int mt = 0; mt < 2; ++mt)
            #pragma unroll
            for (int n = 0; n < 8; ++n)
                #pragma unroll
                for (int e = 0; e < 4; ++e) acc[mt][n][e] = 0.0f;

        #pragma unroll 1
        for (int c = 0; c < 32; ++c) {
            if (c == 31) { CP_WAIT(0); } else { CP_WAIT(1); }
            __syncthreads();
            if (c + 2 < 32) {
                int cn = c + 2;
                const __nv_bfloat16* src = (cn < 16) ? hhi_in : hlo_in;
                int k0 = (cn & 15) * 64;
                uint32_t dst = sb + SM_B + (cn % 3) * B_STG;
                #pragma unroll
                for (int i = 0; i < 4; ++i)
                    cp16(dst + brow[i] * (PIT_B * 2) + bseg[i] * 16,
                         src + (size_t)brow[i] * HID + k0 + bseg[i] * 8);
                CP_COMMIT();
            }
            const __nv_bfloat16* sB = (const __nv_bfloat16*)(smem + SM_B + (c % 3) * B_STG);
            int kb = kq * 16;
            int kA = (c & 15) * 64 + kb;
            uint32_t bfr[8][2];
            #pragma unroll
            for (int n = 0; n < 8; ++n) {
                int nn = n0 + n * 8 + g;
                bfr[n][0] = *(const uint32_t*)&sB[nn * PIT_B + kb + 2 * tc];
                bfr[n][1] = *(const uint32_t*)&sB[nn * PIT_B + kb + 2 * tc + 8];
            }
            #pragma unroll
            for (int mt = 0; mt < 2; ++mt) {
                int r0 = (mt * 16 + g) * PIT_A + kA + 2 * tc;
                int r1 = (mt * 16 + g + 8) * PIT_A + kA + 2 * tc;
                uint32_t a0 = *(const uint32_t*)&sAhi[r0];
                uint32_t a1 = *(const uint32_t*)&sAhi[r1];
                uint32_t a2 = *(const uint32_t*)&sAhi[r0 + 8];
                uint32_t a3 = *(const uint32_t*)&sAhi[r1 + 8];
                #pragma unroll
                for (int n = 0; n < 8; ++n)
                    mma16816(acc[mt][n], a0, a1, a2, a3, bfr[n][0], bfr[n][1]);
            }
            if (c < 16) {
                #pragma unroll
                for (int mt = 0; mt < 2; ++mt) {
                    int r0 = (mt * 16 + g) * PIT_A + kA + 2 * tc;
                    int r1 = (mt * 16 + g + 8) * PIT_A + kA + 2 * tc;
                    uint32_t a0 = *(const uint32_t*)&sAlo[r0];
                    uint32_t a1 = *(const uint32_t*)&sAlo[r1];
                    uint32_t a2 = *(const uint32_t*)&sAlo[r0 + 8];
                    uint32_t a3 = *(const uint32_t*)&sAlo[r1 + 8];
                    #pragma unroll
                    for (int n = 0; n < 8; ++n)
                        mma16816(acc[mt][n], a0, a1, a2, a3, bfr[n][0], bfr[n][1]);
                }
            }
        }
        __syncthreads();   // all MMA done; B stages free for Gsm

        // ---- reduce k-quarters into Gsm (4 phases) ----
        #pragma unroll 1
        for (int ph = 0; ph < 4; ++ph) {
            if (kq == ph) {
                #pragma unroll
                for (int mt = 0; mt < 2; ++mt) {
                    #pragma unroll
                    for (int n = 0; n < 8; ++n) {
                        int row = mt * 16 + g, col = n0 + n * 8 + 2 * tc;
                        float2* p0 = (float2*)&Gsm[row * 132 + col];
                        float2* p1 = (float2*)&Gsm[(row + 8) * 132 + col];
                        if (ph == 0) {
                            *p0 = make_float2(acc[mt][n][0], acc[mt][n][1]);
                            *p1 = make_float2(acc[mt][n][2], acc[mt][n][3]);
                        } else {
                            float2 v0 = *p0, v1 = *p1;
                            v0.x += acc[mt][n][0]; v0.y += acc[mt][n][1];
                            v1.x += acc[mt][n][2]; v1.y += acc[mt][n][3];
                            *p0 = v0; *p1 = v1;
                        }
                    }
                }
            }
            __syncthreads();
        }

        // ---- LSTM cell (c in regs) ----
        {
            int dl0 = cdg * 4;
            float hv[4];
            #pragma unroll
            for (int l = 0; l < 4; ++l) {
                int dl = dl0 + l;
                float zi = Gsm[(0 + dl) * 132 + cb]  + Psm[(0 + dl) * 128 + cb];
                float zf = Gsm[(8 + dl) * 132 + cb]  + Psm[(8 + dl) * 128 + cb];
                float zg = Gsm[(16 + dl) * 132 + cb] + Psm[(16 + dl) * 128 + cb];
                float zo = Gsm[(24 + dl) * 132 + cb] + Psm[(24 + dl) * 128 + cb];
                float iv = sigf(zi), fv = sigf(zf), gv = tanhf(zg), ov = sigf(zo);
                creg[l] = fv * creg[l] + iv * gv;
                hv[l] = ov * tanhf(creg[l]);
            }
            size_t hbase = (size_t)cb * HID + ct * 8 + dl0;
            __nv_bfloat16 hb[4]; float lov[4];
            #pragma unroll
            for (int l = 0; l < 4; ++l) {
                hb[l] = __float2bfloat16(hv[l]);
                lov[l] = hv[l] - __bfloat162float(hb[l]);
            }
            __nv_bfloat162 p01; p01.x = hb[0]; p01.y = hb[1];
            __nv_bfloat162 p23; p23.x = hb[2]; p23.y = hb[3];
            *(__nv_bfloat162*)&hhi_out[hbase]     = p01;
            *(__nv_bfloat162*)&hhi_out[hbase + 2] = p23;
            __nv_bfloat162 q01; q01.x = __float2bfloat16(lov[0]); q01.y = __float2bfloat16(lov[1]);
            __nv_bfloat162 q23; q23.x = __float2bfloat16(lov[2]); q23.y = __float2bfloat16(lov[3]);
            *(__nv_bfloat162*)&hlo_out[hbase]     = q01;
            *(__nv_bfloat162*)&hlo_out[hbase + 2] = q23;
        }

        // ---- global barrier ----
        __threadfence();
        __syncthreads();
        if (tid == 0) {
            atomicAdd(&g_bar, 1u);
            unsigned target = 128u * (unsigned)(s + 1);
            volatile unsigned* vb = &g_bar;
            while (*vb < target) __nanosleep(128);
            __threadfence();
        }
        __syncthreads();
    }
}

// ---------------- classifier ----------------
__global__ void out_kernel(const float* __restrict__ W_out,
                           const float* __restrict__ b_out,
                           float* __restrict__ out) {
    int c = blockIdx.x, b = blockIdx.y;
    const __nv_bfloat16* hh = g_hhi[0] + (size_t)b * HID;
    const __nv_bfloat16* hl = g_hlo[0] + (size_t)b * HID;
    float sum = 0.0f;
    for (int d = threadIdx.x; d < HID; d += 128)
        sum += (__bfloat162float(hh[d]) + __bfloat162float(hl[d])) * W_out[c * HID + d];
    #pragma unroll
    for (int o = 16; o; o >>= 1) sum += __shfl_xor_sync(0xFFFFFFFFu, sum, o);
    __shared__ float red[4];
    if ((threadIdx.x & 31) == 0) red[threadIdx.x >> 5] = sum;
    __syncthreads();
    if (threadIdx.x == 0)
        out[b * NCLS + c] = red[0] + red[1] + red[2] + red[3] + b_out[c];
}

extern "C" void kernel_launch(void* const* d_in, const int* in_sizes, int n_in,
                              void* d_out, int out_size) {
    const float* x     = (const float*)d_in[0];
    const float* h0    = (const float*)d_in[1];
    const float* c0    = (const float*)d_in[2];
    const float* W_ih  = (const float*)d_in[3];
    const float* W_hh  = (const float*)d_in[4];
    const float* b_ih  = (const float*)d_in[5];
    const float* b_hh  = (const float*)d_in[6];
    const float* W_out = (const float*)d_in[7];
    const float* b_out = (const float*)d_in[8];
    float* out = (float*)d_out;

    cudaFuncSetAttribute(step_persist, cudaFuncAttributeMaxDynamicSharedMemorySize, STEP_SMEM);

    init_state<<<BATCH * HID / 256, 256>>>(h0);
    xproj_kernel<<<dim3(64, SEQ), 256>>>(x, W_ih, b_ih, b_hh);
    step_persist<<<128, 256, STEP_SMEM>>>(W_hh, c0);
    out_kernel<<<dim3(NCLS, BATCH), 128>>>(W_out, b_out, out);
}

// round 6
// speedup vs baseline: 1.6303x; 1.0250x over previous
#include <cuda_runtime.h>
#include <cuda_bf16.h>
#include <cstdint>
#include <math.h>

#define BATCH 128
#define SEQ   512
#define INDIM 256
#define HID   1024
#define NCLS  10
#define PSTEP (4 * HID * BATCH)

// ---------------- device globals ----------------
__device__ float g_P[(size_t)SEQ * PSTEP];   // [s][q(4096)][b(128)], q = gate*1024 + d
__device__ __align__(16) __nv_bfloat16 g_hhi[2][BATCH * HID];   // [b][d]
__device__ __align__(16) __nv_bfloat16 g_hlo[2][BATCH * HID];   // [b][d]
__device__ unsigned g_bar;
__device__ volatile unsigned g_flag;

__device__ __forceinline__ uint32_t smem_u32(const void* p) {
    uint32_t a;
    asm("{ .reg .u64 t; cvta.to.shared.u64 t, %1; cvt.u32.u64 %0, t; }" : "=r"(a) : "l"(p));
    return a;
}
__device__ __forceinline__ void cp16(uint32_t dst, const void* src) {
    asm volatile("cp.async.cg.shared.global [%0], [%1], 16;" :: "r"(dst), "l"(src));
}
#define CP_COMMIT() asm volatile("cp.async.commit_group;" ::: "memory")
#define CP_WAIT(n)  asm volatile("cp.async.wait_group %0;" :: "n"(n) : "memory")

__device__ __forceinline__ void ldm_x4(uint32_t &r0, uint32_t &r1, uint32_t &r2,
                                       uint32_t &r3, uint32_t addr) {
    asm volatile("ldmatrix.sync.aligned.m8n8.x4.shared.b16 {%0,%1,%2,%3}, [%4];"
        : "=r"(r0), "=r"(r1), "=r"(r2), "=r"(r3) : "r"(addr));
}
__device__ __forceinline__ void mma16816(float* c, uint32_t a0, uint32_t a1,
                                         uint32_t a2, uint32_t a3,
                                         uint32_t b0, uint32_t b1) {
    asm volatile(
        "mma.sync.aligned.m16n8k16.row.col.f32.bf16.bf16.f32 "
        "{%0,%1,%2,%3}, {%4,%5,%6,%7}, {%8,%9}, {%0,%1,%2,%3};"
        : "+f"(c[0]), "+f"(c[1]), "+f"(c[2]), "+f"(c[3])
        : "r"(a0), "r"(a1), "r"(a2), "r"(a3), "r"(b0), "r"(b1));
}
__device__ __forceinline__ float sigf(float x) { return 1.0f / (1.0f + __expf(-x)); }

// ---------------- init ----------------
__global__ void init_state(const float* __restrict__ h0) {
    int idx = blockIdx.x * 256 + threadIdx.x;   // over [b][d]
    if (idx == 0) { g_bar = 0; g_flag = 0; }
    float h = h0[idx];
    __nv_bfloat16 hi = __float2bfloat16(h);
    g_hhi[0][idx] = hi;
    g_hlo[0][idx] = __float2bfloat16(h - __bfloat162float(hi));
}

// ---------------- x projection (FFMA2, proven) ----------------
__device__ __forceinline__ double pk2(float x, float y) {
    double r; asm("mov.b64 %0, {%1, %2};" : "=d"(r) : "f"(x), "f"(y)); return r;
}
__device__ __forceinline__ void unpk2(double d, float &x, float &y) {
    asm("mov.b64 {%0, %1}, %2;" : "=f"(x), "=f"(y) : "d"(d));
}
__device__ __forceinline__ double ffma2(double a, double b, double c) {
    double r; asm("fma.rn.f32x2 %0, %1, %2, %3;" : "=d"(r) : "d"(a), "d"(b), "d"(c)); return r;
}

__global__ __launch_bounds__(256) void xproj_kernel(
        const float* __restrict__ x, const float* __restrict__ W_ih,
        const float* __restrict__ b_ih, const float* __restrict__ b_hh) {
    __shared__ float Xs[32][132];
    __shared__ float Ws[32][68];
    int tid = threadIdx.x, lane = tid & 31, w = tid >> 5;
    int qt = blockIdx.x, s = blockIdx.y;
    int q0 = w * 8, b0 = lane * 4;

    int xb[4], xk[4]; const float* xp[4];
    #pragma unroll
    for (int it = 0; it < 4; ++it) {
        int f = tid + it * 256;
        xb[it] = f >> 3; xk[it] = (f & 7) * 4;
        xp[it] = x + (size_t)xb[it] * (SEQ * INDIM) + s * INDIM + xk[it];
    }
    int wq[2], wk[2]; const float* wp[2];
    #pragma unroll
    for (int it = 0; it < 2; ++it) {
        int f = tid + it * 256;
        wq[it] = f >> 3; wk[it] = (f & 7) * 4;
        wp[it] = W_ih + (size_t)(qt * 64 + wq[it]) * INDIM + wk[it];
    }
    float4 xR[4], wR[2];
    #pragma unroll
    for (int it = 0; it < 4; ++it) xR[it] = *(const float4*)xp[it];
    #pragma unroll
    for (int it = 0; it < 2; ++it) wR[it] = *(const float4*)wp[it];

    double acc[4][4];
    #pragma unroll
    for (int p = 0; p < 4; ++p)
        #pragma unroll
        for (int bb = 0; bb < 4; ++bb) acc[p][bb] = 0.0;

    #pragma unroll 1
    for (int c = 0; c < 8; ++c) {
        #pragma unroll
        for (int it = 0; it < 4; ++it) {
            Xs[xk[it]+0][xb[it]] = xR[it].x; Xs[xk[it]+1][xb[it]] = xR[it].y;
            Xs[xk[it]+2][xb[it]] = xR[it].z; Xs[xk[it]+3][xb[it]] = xR[it].w;
        }
        #pragma unroll
        for (int it = 0; it < 2; ++it) {
            Ws[wk[it]+0][wq[it]] = wR[it].x; Ws[wk[it]+1][wq[it]] = wR[it].y;
            Ws[wk[it]+2][wq[it]] = wR[it].z; Ws[wk[it]+3][wq[it]] = wR[it].w;
        }
        __syncthreads();
        if (c < 7) {
            int k0 = (c + 1) * 32;
            #pragma unroll
            for (int it = 0; it < 4; ++it) xR[it] = *(const float4*)(xp[it] + k0);
            #pragma unroll
            for (int it = 0; it < 2; ++it) wR[it] = *(const float4*)(wp[it] + k0);
        }
        #pragma unroll 8
        for (int kk = 0; kk < 32; ++kk) {
            float4 xv = *(const float4*)&Xs[kk][b0];
            double2 w01 = *(const double2*)&Ws[kk][q0];
            double2 w23 = *(const double2*)&Ws[kk][q0 + 4];
            double xb0 = pk2(xv.x, xv.x), xb1 = pk2(xv.y, xv.y);
            double xb2 = pk2(xv.z, xv.z), xb3 = pk2(xv.w, xv.w);
            acc[0][0] = ffma2(w01.x, xb0, acc[0][0]);
            acc[0][1] = ffma2(w01.x, xb1, acc[0][1]);
            acc[0][2] = ffma2(w01.x, xb2, acc[0][2]);
            acc[0][3] = ffma2(w01.x, xb3, acc[0][3]);
            acc[1][0] = ffma2(w01.y, xb0, acc[1][0]);
            acc[1][1] = ffma2(w01.y, xb1, acc[1][1]);
            acc[1][2] = ffma2(w01.y, xb2, acc[1][2]);
            acc[1][3] = ffma2(w01.y, xb3, acc[1][3]);
            acc[2][0] = ffma2(w23.x, xb0, acc[2][0]);
            acc[2][1] = ffma2(w23.x, xb1, acc[2][1]);
            acc[2][2] = ffma2(w23.x, xb2, acc[2][2]);
            acc[2][3] = ffma2(w23.x, xb3, acc[2][3]);
            acc[3][0] = ffma2(w23.y, xb0, acc[3][0]);
            acc[3][1] = ffma2(w23.y, xb1, acc[3][1]);
            acc[3][2] = ffma2(w23.y, xb2, acc[3][2]);
            acc[3][3] = ffma2(w23.y, xb3, acc[3][3]);
        }
        __syncthreads();
    }
    size_t sbase = (size_t)s * PSTEP;
    #pragma unroll
    for (int p = 0; p < 4; ++p) {
        int qlo = qt * 64 + q0 + 2 * p;
        float blo = b_ih[qlo] + b_hh[qlo];
        float bhi = b_ih[qlo + 1] + b_hh[qlo + 1];
        float lo[4], hi[4];
        #pragma unroll
        for (int bb = 0; bb < 4; ++bb) unpk2(acc[p][bb], lo[bb], hi[bb]);
        float4 vlo = make_float4(lo[0] + blo, lo[1] + blo, lo[2] + blo, lo[3] + blo);
        float4 vhi = make_float4(hi[0] + bhi, hi[1] + bhi, hi[2] + bhi, hi[3] + bhi);
        *(float4*)&g_P[sbase + (size_t)qlo * BATCH + b0]       = vlo;
        *(float4*)&g_P[sbase + (size_t)(qlo + 1) * BATCH + b0] = vhi;
    }
}

// ---------------- persistent LSTM recurrence ----------------
#define PIT_A 1032
#define PIT_B 72
#define B_STG 18432
#define SM_A_HI 0
#define SM_A_LO 66048
#define SM_P    132096
#define SM_B    148480
#define SM_G    SM_B
#define STEP_SMEM (SM_B + 3 * B_STG)   /* 203776 */

__global__ __launch_bounds__(256, 1) void step_persist(
        const float* __restrict__ W_hh, const float* __restrict__ c0) {
    extern __shared__ char smem[];
    uint32_t sb = smem_u32(smem);
    int tid = threadIdx.x, lane = tid & 31, wid = tid >> 5;
    int g = lane >> 2, tc = lane & 3;
    int ct = blockIdx.x;
    int nh = wid & 1, kq = wid >> 1;       // n-half, k-quarter
    int n0 = nh * 64;

    __nv_bfloat16* sAhi = (__nv_bfloat16*)(smem + SM_A_HI);   // [32][1032]
    __nv_bfloat16* sAlo = (__nv_bfloat16*)(smem + SM_A_LO);
    float* Psm = (float*)(smem + SM_P);                        // [32][128]
    float* Gsm = (float*)(smem + SM_G);                        // [32][132]

    // ---- load + split A once ----
    {
        int lr = tid >> 3, seg = tid & 7;
        int gate = lr >> 3, jd = lr & 7;
        const float* src = W_hh + (size_t)(gate * HID + ct * 8 + jd) * HID + seg * 128;
        #pragma unroll 4
        for (int i = 0; i < 32; ++i) {
            float4 v = *(const float4*)(src + i * 4);
            int k = seg * 128 + i * 4;
            __nv_bfloat16 h0 = __float2bfloat16(v.x);
            __nv_bfloat16 h1 = __float2bfloat16(v.y);
            __nv_bfloat16 h2 = __float2bfloat16(v.z);
            __nv_bfloat16 h3 = __float2bfloat16(v.w);
            sAhi[lr * PIT_A + k + 0] = h0;
            sAhi[lr * PIT_A + k + 1] = h1;
            sAhi[lr * PIT_A + k + 2] = h2;
            sAhi[lr * PIT_A + k + 3] = h3;
            sAlo[lr * PIT_A + k + 0] = __float2bfloat16(v.x - __bfloat162float(h0));
            sAlo[lr * PIT_A + k + 1] = __float2bfloat16(v.y - __bfloat162float(h1));
            sAlo[lr * PIT_A + k + 2] = __float2bfloat16(v.z - __bfloat162float(h2));
            sAlo[lr * PIT_A + k + 3] = __float2bfloat16(v.w - __bfloat162float(h3));
        }
    }

    // ---- c-state in registers ----
    int cb = tid & 127, cdg = tid >> 7;    // batch, dim-group(4)
    float creg[4];
    {
        float4 cv = *(const float4*)&c0[(size_t)cb * HID + ct * 8 + cdg * 4];
        creg[0] = cv.x; creg[1] = cv.y; creg[2] = cv.z; creg[3] = cv.w;
    }

    // ---- ldmatrix address bases (byte offsets from sb) ----
    // A: x4 tile order [m0-7,k0-7][m8-15,k0-7][m0-7,k8-15][m8-15,k8-15]
    int li = lane >> 3, l7 = lane & 7;
    uint32_t aBase[2];   // per m-tile, A-hi base; A-lo = +66048
    #pragma unroll
    for (int mt = 0; mt < 2; ++mt) {
        int row = mt * 16 + (li & 1) * 8 + l7;
        aBase[mt] = sb + SM_A_HI + (uint32_t)row * (PIT_A * 2) + (li >> 1) * 16 + kq * 32;
    }
    // B: x4 tile order [n0-7,k0-7][n0-7,k8-15][n8-15,k0-7][n8-15,k8-15]
    uint32_t bBase[4];   // per n-pair, offset within stage
    #pragma unroll
    for (int p = 0; p < 4; ++p) {
        int row = n0 + p * 16 + (li >> 1) * 8 + l7;
        bBase[p] = (uint32_t)row * (PIT_B * 2) + (li & 1) * 16 + kq * 32;
    }

    // B loader coords
    int brow[4], bseg[4];
    #pragma unroll
    for (int i = 0; i < 4; ++i) { int u = tid + i * 256; brow[i] = u >> 3; bseg[i] = u & 7; }
    // P loader coords
    int pq[4], ps[4];
    #pragma unroll
    for (int i = 0; i < 4; ++i) { int u = tid + i * 256; pq[i] = u >> 5; ps[i] = u & 31; }

    __syncthreads();

    // prefetch P(0)
    {
        const float* Pg = g_P;
        #pragma unroll
        for (int i = 0; i < 4; ++i) {
            int qg = (pq[i] >> 3) * HID + ct * 8 + (pq[i] & 7);
            cp16(sb + SM_P + pq[i] * 512 + ps[i] * 16, Pg + (size_t)qg * BATCH + ps[i] * 4);
        }
        CP_COMMIT();
    }

    #pragma unroll 1
    for (int s = 0; s < SEQ; ++s) {
        const __nv_bfloat16* hhi_in = g_hhi[s & 1];
        const __nv_bfloat16* hlo_in = g_hlo[s & 1];
        __nv_bfloat16* hhi_out = g_hhi[(s + 1) & 1];
        __nv_bfloat16* hlo_out = g_hlo[(s + 1) & 1];

        // issue B chunk0, chunk1
        #pragma unroll
        for (int i = 0; i < 4; ++i)
            cp16(sb + SM_B + brow[i] * (PIT_B * 2) + bseg[i] * 16,
                 hhi_in + (size_t)brow[i] * HID + bseg[i] * 8);
        CP_COMMIT();
        #pragma unroll
        for (int i = 0; i < 4; ++i)
            cp16(sb + SM_B + B_STG + brow[i] * (PIT_B * 2) + bseg[i] * 16,
                 hhi_in + (size_t)brow[i] * HID + 64 + bseg[i] * 8);
        CP_COMMIT();

        float acc[2][8][4];
        #pragma unroll
        for (int mt = 0; mt < 2; ++mt)
            #pragma unroll
            for (int n = 0; n < 8; ++n)
                #pragma unroll
                for (int e = 0; e < 4; ++e) acc[mt][n][e] = 0.0f;

        #pragma unroll 1
        for (int c = 0; c < 32; ++c) {
            if (c == 31) { CP_WAIT(0); } else { CP_WAIT(1); }
            __syncthreads();
            if (c + 2 < 32) {
                int cn = c + 2;
                const __nv_bfloat16* src = (cn < 16) ? hhi_in : hlo_in;
                int k0 = (cn & 15) * 64;
                uint32_t dst = sb + SM_B + (cn % 3) * B_STG;
                #pragma unroll
                for (int i = 0; i < 4; ++i)
                    cp16(dst + brow[i] * (PIT_B * 2) + bseg[i] * 16,
                         src + (size_t)brow[i] * HID + k0 + bseg[i] * 8);
                CP_COMMIT();
            }
            uint32_t stOff = SM_B + (c % 3) * B_STG;
            uint32_t kByte = (uint32_t)(c & 15) * 128;   // chunk k-offset in bytes

            uint32_t bfr[8][2];
            #pragma unroll
            for (int p = 0; p < 4; ++p)
                ldm_x4(bfr[2*p][0], bfr[2*p][1], bfr[2*p+1][0], bfr[2*p+1][1],
                       sb + stOff + bBase[p]);
            uint32_t ah[2][4];
            #pragma unroll
            for (int mt = 0; mt < 2; ++mt)
                ldm_x4(ah[mt][0], ah[mt][1], ah[mt][2], ah[mt][3], aBase[mt] + kByte);
            #pragma unroll
            for (int mt = 0; mt < 2; ++mt)
                #pragma unroll
                for (int n = 0; n < 8; ++n)
                    mma16816(acc[mt][n], ah[mt][0], ah[mt][1], ah[mt][2], ah[mt][3],
                             bfr[n][0], bfr[n][1]);
            if (c < 16) {
                uint32_t al[2][4];
                #pragma unroll
                for (int mt = 0; mt < 2; ++mt)
                    ldm_x4(al[mt][0], al[mt][1], al[mt][2], al[mt][3],
                           aBase[mt] + 66048u + kByte);
                #pragma unroll
                for (int mt = 0; mt < 2; ++mt)
                    #pragma unroll
                    for (int n = 0; n < 8; ++n)
                        mma16816(acc[mt][n], al[mt][0], al[mt][1], al[mt][2], al[mt][3],
                                 bfr[n][0], bfr[n][1]);
            }
        }
        __syncthreads();   // all MMA done; B stages free for Gsm

        // ---- reduce k-quarters into Gsm (4 phases) ----
        #pragma unroll 1
        for (int ph = 0; ph < 4; ++ph) {
            if (kq == ph) {
                #pragma unroll
                for (int mt = 0; mt < 2; ++mt) {
                    #pragma unroll
                    for (int n = 0; n < 8; ++n) {
                        int row = mt * 16 + g, col = n0 + n * 8 + 2 * tc;
                        float2* p0 = (float2*)&Gsm[row * 132 + col];
                        float2* p1 = (float2*)&Gsm[(row + 8) * 132 + col];
                        if (ph == 0) {
                            *p0 = make_float2(acc[mt][n][0], acc[mt][n][1]);
                            *p1 = make_float2(acc[mt][n][2], acc[mt][n][3]);
                        } else {
                            float2 v0 = *p0, v1 = *p1;
                            v0.x += acc[mt][n][0]; v0.y += acc[mt][n][1];
                            v1.x += acc[mt][n][2]; v1.y += acc[mt][n][3];
                            *p0 = v0; *p1 = v1;
                        }
                    }
                }
            }
            __syncthreads();
        }

        // ---- LSTM cell (c in regs) ----
        {
            int dl0 = cdg * 4;
            float hv[4];
            #pragma unroll
            for (int l = 0; l < 4; ++l) {
                int dl = dl0 + l;
                float zi = Gsm[(0 + dl) * 132 + cb]  + Psm[(0 + dl) * 128 + cb];
                float zf = Gsm[(8 + dl) * 132 + cb]  + Psm[(8 + dl) * 128 + cb];
                float zg = Gsm[(16 + dl) * 132 + cb] + Psm[(16 + dl) * 128 + cb];
                float zo = Gsm[(24 + dl) * 132 + cb] + Psm[(24 + dl) * 128 + cb];
                float iv = sigf(zi), fv = sigf(zf), gv = tanhf(zg), ov = sigf(zo);
                creg[l] = fv * creg[l] + iv * gv;
                hv[l] = ov * tanhf(creg[l]);
            }
            size_t hbase = (size_t)cb * HID + ct * 8 + dl0;
            __nv_bfloat16 hb[4]; float lov[4];
            #pragma unroll
            for (int l = 0; l < 4; ++l) {
                hb[l] = __float2bfloat16(hv[l]);
                lov[l] = hv[l] - __bfloat162float(hb[l]);
            }
            __nv_bfloat162 p01; p01.x = hb[0]; p01.y = hb[1];
            __nv_bfloat162 p23; p23.x = hb[2]; p23.y = hb[3];
            *(__nv_bfloat162*)&hhi_out[hbase]     = p01;
            *(__nv_bfloat162*)&hhi_out[hbase + 2] = p23;
            __nv_bfloat162 q01; q01.x = __float2bfloat16(lov[0]); q01.y = __float2bfloat16(lov[1]);
            __nv_bfloat162 q23; q23.x = __float2bfloat16(lov[2]); q23.y = __float2bfloat16(lov[3]);
            *(__nv_bfloat162*)&hlo_out[hbase]     = q01;
            *(__nv_bfloat162*)&hlo_out[hbase + 2] = q23;
        }

        // ---- arrive ----
        __threadfence();
        __syncthreads();
        unsigned target = (unsigned)(s + 1);
        if (tid == 0) {
            unsigned old = atomicAdd(&g_bar, 1u);
            if (old == 128u * target - 1u) g_flag = target;   // last arriver publishes
        }

        // ---- overlap: prefetch P(s+1) while others finish ----
        if (s + 1 < SEQ) {
            const float* Pg = g_P + (size_t)(s + 1) * PSTEP;
            #pragma unroll
            for (int i = 0; i < 4; ++i) {
                int qg = (pq[i] >> 3) * HID + ct * 8 + (pq[i] & 7);
                cp16(sb + SM_P + pq[i] * 512 + ps[i] * 16, Pg + (size_t)qg * BATCH + ps[i] * 4);
            }
            CP_COMMIT();
        }

        // ---- wait ----
        if (tid == 0) {
            while (g_flag < target) { }
            __threadfence();
        }
        __syncthreads();
    }
}

// ---------------- classifier ----------------
__global__ void out_kernel(const float* __restrict__ W_out,
                           const float* __restrict__ b_out,
                           float* __restrict__ out) {
    int c = blockIdx.x, b = blockIdx.y;
    const __nv_bfloat16* hh = g_hhi[0] + (size_t)b * HID;
    const __nv_bfloat16* hl = g_hlo[0] + (size_t)b * HID;
    float sum = 0.0f;
    for (int d = threadIdx.x; d < HID; d += 128)
        sum += (__bfloat162float(hh[d]) + __bfloat162float(hl[d])) * W_out[c * HID + d];
    #pragma unroll
    for (int o = 16; o; o >>= 1) sum += __shfl_xor_sync(0xFFFFFFFFu, sum, o);
    __shared__ float red[4];
    if ((threadIdx.x & 31) == 0) red[threadIdx.x >> 5] = sum;
    __syncthreads();
    if (threadIdx.x == 0)
        out[b * NCLS + c] = red[0] + red[1] + red[2] + red[3] + b_out[c];
}

extern "C" void kernel_launch(void* const* d_in, const int* in_sizes, int n_in,
                              void* d_out, int out_size) {
    const float* x     = (const float*)d_in[0];
    const float* h0    = (const float*)d_in[1];
    const float* c0    = (const float*)d_in[2];
    const float* W_ih  = (const float*)d_in[3];
    const float* W_hh  = (const float*)d_in[4];
    const float* b_ih  = (const float*)d_in[5];
    const float* b_hh  = (const float*)d_in[6];
    const float* W_out = (const float*)d_in[7];
    const float* b_out = (const float*)d_in[8];
    float* out = (float*)d_out;

    cudaFuncSetAttribute(step_persist, cudaFuncAttributeMaxDynamicSharedMemorySize, STEP_SMEM);

    init_state<<<BATCH * HID / 256, 256>>>(h0);
    xproj_kernel<<<dim3(64, SEQ), 256>>>(x, W_ih, b_ih, b_hh);
    step_persist<<<128, 256, STEP_SMEM>>>(W_hh, c0);
    out_kernel<<<dim3(NCLS, BATCH), 128>>>(W_out, b_out, out);
}

// round 8
// speedup vs baseline: 2.0413x; 1.2521x over previous
#include <cuda_runtime.h>
#include <cuda_bf16.h>
#include <cstdint>
#include <math.h>

#define BATCH 128
#define SEQ   512
#define INDIM 256
#define HID   1024
#define NCLS  10
#define PSTEP (4 * HID * BATCH)

// ---------------- device globals ----------------
__device__ float g_P[(size_t)SEQ * PSTEP];   // [s][q(4096)][b(128)], q = gate*1024 + d
__device__ __align__(16) __nv_bfloat16 g_hhi[2][BATCH * HID];   // [b][d]
__device__ __align__(16) __nv_bfloat16 g_hlo[2][BATCH * HID];   // [b][d]
__device__ unsigned g_bar;
__device__ volatile unsigned g_flag;

__device__ __forceinline__ uint32_t smem_u32(const void* p) {
    uint32_t a;
    asm("{ .reg .u64 t; cvta.to.shared.u64 t, %1; cvt.u32.u64 %0, t; }" : "=r"(a) : "l"(p));
    return a;
}
__device__ __forceinline__ void cp16(uint32_t dst, const void* src) {
    asm volatile("cp.async.cg.shared.global [%0], [%1], 16;" :: "r"(dst), "l"(src));
}
#define CP_COMMIT() asm volatile("cp.async.commit_group;" ::: "memory")
#define CP_WAIT(n)  asm volatile("cp.async.wait_group %0;" :: "n"(n) : "memory")

__device__ __forceinline__ void ldm_x4(uint32_t &r0, uint32_t &r1, uint32_t &r2,
                                       uint32_t &r3, uint32_t addr) {
    asm volatile("ldmatrix.sync.aligned.m8n8.x4.shared.b16 {%0,%1,%2,%3}, [%4];"
        : "=r"(r0), "=r"(r1), "=r"(r2), "=r"(r3) : "r"(addr));
}
__device__ __forceinline__ void mma16816(float* c, uint32_t a0, uint32_t a1,
                                         uint32_t a2, uint32_t a3,
                                         uint32_t b0, uint32_t b1) {
    asm volatile(
        "mma.sync.aligned.m16n8k16.row.col.f32.bf16.bf16.f32 "
        "{%0,%1,%2,%3}, {%4,%5,%6,%7}, {%8,%9}, {%0,%1,%2,%3};"
        : "+f"(c[0]), "+f"(c[1]), "+f"(c[2]), "+f"(c[3])
        : "r"(a0), "r"(a1), "r"(a2), "r"(a3), "r"(b0), "r"(b1));
}
__device__ __forceinline__ float sigf(float x) { return 1.0f / (1.0f + __expf(-x)); }

// ---------------- init ----------------
__global__ void init_state(const float* __restrict__ h0) {
    int idx = blockIdx.x * 256 + threadIdx.x;   // over [b][d]
    if (idx == 0) { g_bar = 0; g_flag = 0; }
    float h = h0[idx];
    __nv_bfloat16 hi = __float2bfloat16(h);
    g_hhi[0][idx] = hi;
    g_hlo[0][idx] = __float2bfloat16(h - __bfloat162float(hi));
}

// ---------------- x projection (FFMA2, proven) ----------------
__device__ __forceinline__ double pk2(float x, float y) {
    double r; asm("mov.b64 %0, {%1, %2};" : "=d"(r) : "f"(x), "f"(y)); return r;
}
__device__ __forceinline__ void unpk2(double d, float &x, float &y) {
    asm("mov.b64 {%0, %1}, %2;" : "=f"(x), "=f"(y) : "d"(d));
}
__device__ __forceinline__ double ffma2(double a, double b, double c) {
    double r; asm("fma.rn.f32x2 %0, %1, %2, %3;" : "=d"(r) : "d"(a), "d"(b), "d"(c)); return r;
}

__global__ __launch_bounds__(256) void xproj_kernel(
        const float* __restrict__ x, const float* __restrict__ W_ih,
        const float* __restrict__ b_ih, const float* __restrict__ b_hh) {
    __shared__ float Xs[32][132];
    __shared__ float Ws[32][68];
    int tid = threadIdx.x, lane = tid & 31, w = tid >> 5;
    int qt = blockIdx.x, s = blockIdx.y;
    int q0 = w * 8, b0 = lane * 4;

    int xb[4], xk[4]; const float* xp[4];
    #pragma unroll
    for (int it = 0; it < 4; ++it) {
        int f = tid + it * 256;
        xb[it] = f >> 3; xk[it] = (f & 7) * 4;
        xp[it] = x + (size_t)xb[it] * (SEQ * INDIM) + s * INDIM + xk[it];
    }
    int wq[2], wk[2]; const float* wp[2];
    #pragma unroll
    for (int it = 0; it < 2; ++it) {
        int f = tid + it * 256;
        wq[it] = f >> 3; wk[it] = (f & 7) * 4;
        wp[it] = W_ih + (size_t)(qt * 64 + wq[it]) * INDIM + wk[it];
    }
    float4 xR[4], wR[2];
    #pragma unroll
    for (int it = 0; it < 4; ++it) xR[it] = *(const float4*)xp[it];
    #pragma unroll
    for (int it = 0; it < 2; ++it) wR[it] = *(const float4*)wp[it];

    double acc[4][4];
    #pragma unroll
    for (int p = 0; p < 4; ++p)
        #pragma unroll
        for (int bb = 0; bb < 4; ++bb) acc[p][bb] = 0.0;

    #pragma unroll 1
    for (int c = 0; c < 8; ++c) {
        #pragma unroll
        for (int it = 0; it < 4; ++it) {
            Xs[xk[it]+0][xb[it]] = xR[it].x; Xs[xk[it]+1][xb[it]] = xR[it].y;
            Xs[xk[it]+2][xb[it]] = xR[it].z; Xs[xk[it]+3][xb[it]] = xR[it].w;
        }
        #pragma unroll
        for (int it = 0; it < 2; ++it) {
            Ws[wk[it]+0][wq[it]] = wR[it].x; Ws[wk[it]+1][wq[it]] = wR[it].y;
            Ws[wk[it]+2][wq[it]] = wR[it].z; Ws[wk[it]+3][wq[it]] = wR[it].w;
        }
        __syncthreads();
        if (c < 7) {
            int k0 = (c + 1) * 32;
            #pragma unroll
            for (int it = 0; it < 4; ++it) xR[it] = *(const float4*)(xp[it] + k0);
            #pragma unroll
            for (int it = 0; it < 2; ++it) wR[it] = *(const float4*)(wp[it] + k0);
        }
        #pragma unroll 8
        for (int kk = 0; kk < 32; ++kk) {
            float4 xv = *(const float4*)&Xs[kk][b0];
            double2 w01 = *(const double2*)&Ws[kk][q0];
            double2 w23 = *(const double2*)&Ws[kk][q0 + 4];
            double xb0 = pk2(xv.x, xv.x), xb1 = pk2(xv.y, xv.y);
            double xb2 = pk2(xv.z, xv.z), xb3 = pk2(xv.w, xv.w);
            acc[0][0] = ffma2(w01.x, xb0, acc[0][0]);
            acc[0][1] = ffma2(w01.x, xb1, acc[0][1]);
            acc[0][2] = ffma2(w01.x, xb2, acc[0][2]);
            acc[0][3] = ffma2(w01.x, xb3, acc[0][3]);
            acc[1][0] = ffma2(w01.y, xb0, acc[1][0]);
            acc[1][1] = ffma2(w01.y, xb1, acc[1][1]);
            acc[1][2] = ffma2(w01.y, xb2, acc[1][2]);
            acc[1][3] = ffma2(w01.y, xb3, acc[1][3]);
            acc[2][0] = ffma2(w23.x, xb0, acc[2][0]);
            acc[2][1] = ffma2(w23.x, xb1, acc[2][1]);
            acc[2][2] = ffma2(w23.x, xb2, acc[2][2]);
            acc[2][3] = ffma2(w23.x, xb3, acc[2][3]);
            acc[3][0] = ffma2(w23.y, xb0, acc[3][0]);
            acc[3][1] = ffma2(w23.y, xb1, acc[3][1]);
            acc[3][2] = ffma2(w23.y, xb2, acc[3][2]);
            acc[3][3] = ffma2(w23.y, xb3, acc[3][3]);
        }
        __syncthreads();
    }
    size_t sbase = (size_t)s * PSTEP;
    #pragma unroll
    for (int p = 0; p < 4; ++p) {
        int qlo = qt * 64 + q0 + 2 * p;
        float blo = b_ih[qlo] + b_hh[qlo];
        float bhi = b_ih[qlo + 1] + b_hh[qlo + 1];
        float lo[4], hi[4];
        #pragma unroll
        for (int bb = 0; bb < 4; ++bb) unpk2(acc[p][bb], lo[bb], hi[bb]);
        float4 vlo = make_float4(lo[0] + blo, lo[1] + blo, lo[2] + blo, lo[3] + blo);
        float4 vhi = make_float4(hi[0] + bhi, hi[1] + bhi, hi[2] + bhi, hi[3] + bhi);
        *(float4*)&g_P[sbase + (size_t)qlo * BATCH + b0]       = vlo;
        *(float4*)&g_P[sbase + (size_t)(qlo + 1) * BATCH + b0] = vhi;
    }
}

// ---------------- persistent LSTM recurrence, warp-decoupled ----------------
// 128 CTAs x 256 thr (8 warps). CTA ct: rows = 4 gates x dims [ct*8,ct*8+8).
// Warp w owns batches [w*16, w*16+16), full K, private 3-stage cp.async ring.
// Cell computed in-register from mma fragments (no k-reduce, no gate exchange).
#define PIT_A 1032
#define SM_A_HI 0
#define SM_A_LO 66048
#define SM_P    132096
#define SM_B    148480
#define SLICE_PITCH 144          /* bytes per B-slice row (64 bf16 + 8 pad) */
#define SLICE_STRIDE 2304        /* 16 rows x 144 B */
#define STEP_SMEM (SM_B + 8 * 3 * SLICE_STRIDE)   /* 203776 */

__global__ __launch_bounds__(256, 1) void step_persist(
        const float* __restrict__ W_hh, const float* __restrict__ c0) {
    extern __shared__ char smem[];
    uint32_t sb = smem_u32(smem);
    int tid = threadIdx.x, lane = tid & 31, wid = tid >> 5;
    int li = lane >> 3, l7 = lane & 7;
    int jd = lane >> 2, tc = lane & 3;
    int ct = blockIdx.x;

    __nv_bfloat16* sAhi = (__nv_bfloat16*)(smem + SM_A_HI);   // [32][1032]
    __nv_bfloat16* sAlo = (__nv_bfloat16*)(smem + SM_A_LO);
    float* Psm = (float*)(smem + SM_P);                        // [32][128]

    // ---- load + split A once ----
    {
        int lr = tid >> 3, seg = tid & 7;
        int gate = lr >> 3, jj = lr & 7;
        const float* src = W_hh + (size_t)(gate * HID + ct * 8 + jj) * HID + seg * 128;
        #pragma unroll 4
        for (int i = 0; i < 32; ++i) {
            float4 v = *(const float4*)(src + i * 4);
            int k = seg * 128 + i * 4;
            __nv_bfloat16 h0 = __float2bfloat16(v.x);
            __nv_bfloat16 h1 = __float2bfloat16(v.y);
            __nv_bfloat16 h2 = __float2bfloat16(v.z);
            __nv_bfloat16 h3 = __float2bfloat16(v.w);
            sAhi[lr * PIT_A + k + 0] = h0;
            sAhi[lr * PIT_A + k + 1] = h1;
            sAhi[lr * PIT_A + k + 2] = h2;
            sAhi[lr * PIT_A + k + 3] = h3;
            sAlo[lr * PIT_A + k + 0] = __float2bfloat16(v.x - __bfloat162float(h0));
            sAlo[lr * PIT_A + k + 1] = __float2bfloat16(v.y - __bfloat162float(h1));
            sAlo[lr * PIT_A + k + 2] = __float2bfloat16(v.z - __bfloat162float(h2));
            sAlo[lr * PIT_A + k + 3] = __float2bfloat16(v.w - __bfloat162float(h3));
        }
    }

    // ---- c-state in registers: (dim jd, batches wid*16 + n*8 + 2tc + e) ----
    float creg[2][2];
    {
        int d = ct * 8 + jd;
        #pragma unroll
        for (int n = 0; n < 2; ++n)
            #pragma unroll
            for (int e = 0; e < 2; ++e)
                creg[n][e] = c0[(size_t)(wid * 16 + n * 8 + 2 * tc + e) * HID + d];
    }

    // ---- ldmatrix A bases (per m-tile; add kByte + ks*32; +66048 for lo) ----
    uint32_t aOff[2];
    #pragma unroll
    for (int mt = 0; mt < 2; ++mt) {
        int row = mt * 16 + (li & 1) * 8 + l7;
        aOff[mt] = sb + SM_A_HI + (uint32_t)row * (PIT_A * 2) + (li >> 1) * 16;
    }
    // B ldmatrix offset within slice (add ks*32)
    uint32_t bOff = (uint32_t)((li >> 1) * 8 + l7) * SLICE_PITCH + (li & 1) * 16;
    // B cp coords: 4 cp16/thread covering the 16x64 slice
    int brow[4], bseg[4];
    #pragma unroll
    for (int i = 0; i < 4; ++i) { int u = lane + i * 32; brow[i] = u >> 3; bseg[i] = u & 7; }
    // P loader coords
    int pq[4], ps[4];
    #pragma unroll
    for (int i = 0; i < 4; ++i) { int u = tid + i * 256; pq[i] = u >> 5; ps[i] = u & 31; }

    uint32_t myStage0 = sb + SM_B + (uint32_t)wid * 3 * SLICE_STRIDE;

    __syncthreads();

    // prefetch P(0)
    {
        const float* Pg = g_P;
        #pragma unroll
        for (int i = 0; i < 4; ++i) {
            int qg = (pq[i] >> 3) * HID + ct * 8 + (pq[i] & 7);
            cp16(sb + SM_P + pq[i] * 512 + ps[i] * 16, Pg + (size_t)qg * BATCH + ps[i] * 4);
        }
        CP_COMMIT();
    }

    #pragma unroll 1
    for (int s = 0; s < SEQ; ++s) {
        const __nv_bfloat16* hhi_in = g_hhi[s & 1];
        const __nv_bfloat16* hlo_in = g_hlo[s & 1];
        __nv_bfloat16* hhi_out = g_hhi[(s + 1) & 1];
        __nv_bfloat16* hlo_out = g_hlo[(s + 1) & 1];

        // issue B chunk 0, 1 into private ring
        #pragma unroll
        for (int cc = 0; cc < 2; ++cc) {
            #pragma unroll
            for (int i = 0; i < 4; ++i)
                cp16(myStage0 + cc * SLICE_STRIDE + brow[i] * SLICE_PITCH + bseg[i] * 16,
                     hhi_in + (size_t)(wid * 16 + brow[i]) * HID + cc * 64 + bseg[i] * 8);
            CP_COMMIT();
        }

        float acc[2][2][4];
        #pragma unroll
        for (int mt = 0; mt < 2; ++mt)
            #pragma unroll
            for (int n = 0; n < 2; ++n)
                #pragma unroll
                for (int e = 0; e < 4; ++e) acc[mt][n][e] = 0.0f;

        #pragma unroll 1
        for (int c = 0; c < 32; ++c) {
            if (c == 31) { CP_WAIT(0); } else { CP_WAIT(1); }
            __syncwarp();
            if (c + 2 < 32) {
                int cn = c + 2;
                const __nv_bfloat16* src = (cn < 16) ? hhi_in : hlo_in;
                int k0 = (cn & 15) * 64;
                uint32_t dst = myStage0 + (cn % 3) * SLICE_STRIDE;
                #pragma unroll
                for (int i = 0; i < 4; ++i)
                    cp16(dst + brow[i] * SLICE_PITCH + bseg[i] * 16,
                         src + (size_t)(wid * 16 + brow[i]) * HID + k0 + bseg[i] * 8);
                CP_COMMIT();
            }
            uint32_t stBase = myStage0 + (c % 3) * SLICE_STRIDE;
            uint32_t kByte = (uint32_t)(c & 15) * 128;
            bool doLo = (c < 16);
            #pragma unroll
            for (int ks = 0; ks < 4; ++ks) {
                uint32_t b0, b1, b2, b3;
                ldm_x4(b0, b1, b2, b3, stBase + bOff + ks * 32);
                #pragma unroll
                for (int mt = 0; mt < 2; ++mt) {
                    uint32_t a0, a1, a2, a3;
                    ldm_x4(a0, a1, a2, a3, aOff[mt] + kByte + ks * 32);
                    mma16816(acc[mt][0], a0, a1, a2, a3, b0, b1);
                    mma16816(acc[mt][1], a0, a1, a2, a3, b2, b3);
                }
                if (doLo) {
                    #pragma unroll
                    for (int mt = 0; mt < 2; ++mt) {
                        uint32_t a0, a1, a2, a3;
                        ldm_x4(a0, a1, a2, a3, aOff[mt] + 66048u + kByte + ks * 32);
                        mma16816(acc[mt][0], a0, a1, a2, a3, b0, b1);
                        mma16816(acc[mt][1], a0, a1, a2, a3, b2, b3);
                    }
                }
            }
        }

        // ---- LSTM cell fully in-register (i,f from mt0; g,o from mt1) ----
        {
            int d = ct * 8 + jd;
            #pragma unroll
            for (int n = 0; n < 2; ++n) {
                int col = wid * 16 + n * 8 + 2 * tc;
                float2 pi = *(const float2*)&Psm[(0 * 8 + jd) * 128 + col];
                float2 pf = *(const float2*)&Psm[(1 * 8 + jd) * 128 + col];
                float2 pg = *(const float2*)&Psm[(2 * 8 + jd) * 128 + col];
                float2 po = *(const float2*)&Psm[(3 * 8 + jd) * 128 + col];
                #pragma unroll
                for (int e = 0; e < 2; ++e) {
                    float zi = acc[0][n][e]     + (e ? pi.y : pi.x);
                    float zf = acc[0][n][2 + e] + (e ? pf.y : pf.x);
                    float zg = acc[1][n][e]     + (e ? pg.y : pg.x);
                    float zo = acc[1][n][2 + e] + (e ? po.y : po.x);
                    float iv = sigf(zi), fv = sigf(zf), gv = tanhf(zg), ov = sigf(zo);
                    creg[n][e] = fv * creg[n][e] + iv * gv;
                    float hv = ov * tanhf(creg[n][e]);
                    __nv_bfloat16 hb = __float2bfloat16(hv);
                    size_t hidx = (size_t)(col + e) * HID + d;
                    hhi_out[hidx] = hb;
                    hlo_out[hidx] = __float2bfloat16(hv - __bfloat162float(hb));
                }
            }
        }

        // ---- arrive ----
        __threadfence();
        __syncthreads();
        unsigned target = (unsigned)(s + 1);
        if (tid == 0) {
            unsigned old = atomicAdd(&g_bar, 1u);
            if (old == 128u * target - 1u) g_flag = target;
        }

        // ---- overlap: prefetch P(s+1) during the wait ----
        if (s + 1 < SEQ) {
            const float* Pg = g_P + (size_t)(s + 1) * PSTEP;
            #pragma unroll
            for (int i = 0; i < 4; ++i) {
                int qg = (pq[i] >> 3) * HID + ct * 8 + (pq[i] & 7);
                cp16(sb + SM_P + pq[i] * 512 + ps[i] * 16, Pg + (size_t)qg * BATCH + ps[i] * 4);
            }
            CP_COMMIT();
        }

        // ---- wait ----
        if (tid == 0) {
            while (g_flag < target) { }
            __threadfence();
        }
        __syncthreads();
    }
}

// ---------------- classifier ----------------
__global__ void out_kernel(const float* __restrict__ W_out,
                           const float* __restrict__ b_out,
                           float* __restrict__ out) {
    int c = blockIdx.x, b = blockIdx.y;
    const __nv_bfloat16* hh = g_hhi[0] + (size_t)b * HID;
    const __nv_bfloat16* hl = g_hlo[0] + (size_t)b * HID;
    float sum = 0.0f;
    for (int d = threadIdx.x; d < HID; d += 128)
        sum += (__bfloat162float(hh[d]) + __bfloat162float(hl[d])) * W_out[c * HID + d];
    #pragma unroll
    for (int o = 16; o; o >>= 1) sum += __shfl_xor_sync(0xFFFFFFFFu, sum, o);
    __shared__ float red[4];
    if ((threadIdx.x & 31) == 0) red[threadIdx.x >> 5] = sum;
    __syncthreads();
    if (threadIdx.x == 0)
        out[b * NCLS + c] = red[0] + red[1] + red[2] + red[3] + b_out[c];
}

extern "C" void kernel_launch(void* const* d_in, const int* in_sizes, int n_in,
                              void* d_out, int out_size) {
    const float* x     = (const float*)d_in[0];
    const float* h0    = (const float*)d_in[1];
    const float* c0    = (const float*)d_in[2];
    const float* W_ih  = (const float*)d_in[3];
    const float* W_hh  = (const float*)d_in[4];
    const float* b_ih  = (const float*)d_in[5];
    const float* b_hh  = (const float*)d_in[6];
    const float* W_out = (const float*)d_in[7];
    const float* b_out = (const float*)d_in[8];
    float* out = (float*)d_out;

    cudaFuncSetAttribute(step_persist, cudaFuncAttributeMaxDynamicSharedMemorySize, STEP_SMEM);

    init_state<<<BATCH * HID / 256, 256>>>(h0);
    xproj_kernel<<<dim3(64, SEQ), 256>>>(x, W_ih, b_ih, b_hh);
    step_persist<<<128, 256, STEP_SMEM>>>(W_hh, c0);
    out_kernel<<<dim3(NCLS, BATCH), 128>>>(W_out, b_out, out);
}

// round 9
// speedup vs baseline: 2.7451x; 1.3448x over previous
#include <cuda_runtime.h>
#include <cuda_bf16.h>
#include <cuda_fp16.h>
#include <cstdint>
#include <math.h>

#define BATCH 128
#define SEQ   512
#define INDIM 256
#define HID   1024
#define NCLS  10
#define PSTEP (4 * HID * BATCH)

// ---------------- device globals ----------------
__device__ float g_P[(size_t)SEQ * PSTEP];   // [s][q(4096)][b(128)], q = gate*1024 + d
__device__ __align__(16) __half g_h[2][BATCH * HID];   // [b][d] fp16 state
__device__ float g_hfin[BATCH * HID];                  // final h fp32 for classifier
__device__ unsigned g_bar;
__device__ volatile unsigned g_flag;

__device__ __forceinline__ uint32_t smem_u32(const void* p) {
    uint32_t a;
    asm("{ .reg .u64 t; cvta.to.shared.u64 t, %1; cvt.u32.u64 %0, t; }" : "=r"(a) : "l"(p));
    return a;
}
__device__ __forceinline__ void cp16(uint32_t dst, const void* src) {
    asm volatile("cp.async.cg.shared.global [%0], [%1], 16;" :: "r"(dst), "l"(src));
}
#define CP_COMMIT() asm volatile("cp.async.commit_group;" ::: "memory")
#define CP_WAIT(n)  asm volatile("cp.async.wait_group %0;" :: "n"(n) : "memory")

__device__ __forceinline__ void ldm_x4(uint32_t &r0, uint32_t &r1, uint32_t &r2,
                                       uint32_t &r3, uint32_t addr) {
    asm volatile("ldmatrix.sync.aligned.m8n8.x4.shared.b16 {%0,%1,%2,%3}, [%4];"
        : "=r"(r0), "=r"(r1), "=r"(r2), "=r"(r3) : "r"(addr));
}
__device__ __forceinline__ void mma16816(float* c, uint32_t a0, uint32_t a1,
                                         uint32_t a2, uint32_t a3,
                                         uint32_t b0, uint32_t b1) {
    asm volatile(
        "mma.sync.aligned.m16n8k16.row.col.f32.f16.f16.f32 "
        "{%0,%1,%2,%3}, {%4,%5,%6,%7}, {%8,%9}, {%0,%1,%2,%3};"
        : "+f"(c[0]), "+f"(c[1]), "+f"(c[2]), "+f"(c[3])
        : "r"(a0), "r"(a1), "r"(a2), "r"(a3), "r"(b0), "r"(b1));
}
__device__ __forceinline__ float sigf(float x) { return 1.0f / (1.0f + __expf(-x)); }

// ---------------- init ----------------
__global__ void init_state(const float* __restrict__ h0) {
    int idx = blockIdx.x * 256 + threadIdx.x;   // over [b][d]
    if (idx == 0) { g_bar = 0; g_flag = 0; }
    g_h[0][idx] = __float2half(h0[idx]);
}

// ---------------- x projection (FFMA2, proven) ----------------
__device__ __forceinline__ double pk2(float x, float y) {
    double r; asm("mov.b64 %0, {%1, %2};" : "=d"(r) : "f"(x), "f"(y)); return r;
}
__device__ __forceinline__ void unpk2(double d, float &x, float &y) {
    asm("mov.b64 {%0, %1}, %2;" : "=f"(x), "=f"(y) : "d"(d));
}
__device__ __forceinline__ double ffma2(double a, double b, double c) {
    double r; asm("fma.rn.f32x2 %0, %1, %2, %3;" : "=d"(r) : "d"(a), "d"(b), "d"(c)); return r;
}

__global__ __launch_bounds__(256) void xproj_kernel(
        const float* __restrict__ x, const float* __restrict__ W_ih,
        const float* __restrict__ b_ih, const float* __restrict__ b_hh) {
    __shared__ float Xs[32][132];
    __shared__ float Ws[32][68];
    int tid = threadIdx.x, lane = tid & 31, w = tid >> 5;
    int qt = blockIdx.x, s = blockIdx.y;
    int q0 = w * 8, b0 = lane * 4;

    int xb[4], xk[4]; const float* xp[4];
    #pragma unroll
    for (int it = 0; it < 4; ++it) {
        int f = tid + it * 256;
        xb[it] = f >> 3; xk[it] = (f & 7) * 4;
        xp[it] = x + (size_t)xb[it] * (SEQ * INDIM) + s * INDIM + xk[it];
    }
    int wq[2], wk[2]; const float* wp[2];
    #pragma unroll
    for (int it = 0; it < 2; ++it) {
        int f = tid + it * 256;
        wq[it] = f >> 3; wk[it] = (f & 7) * 4;
        wp[it] = W_ih + (size_t)(qt * 64 + wq[it]) * INDIM + wk[it];
    }
    float4 xR[4], wR[2];
    #pragma unroll
    for (int it = 0; it < 4; ++it) xR[it] = *(const float4*)xp[it];
    #pragma unroll
    for (int it = 0; it < 2; ++it) wR[it] = *(const float4*)wp[it];

    double acc[4][4];
    #pragma unroll
    for (int p = 0; p < 4; ++p)
        #pragma unroll
        for (int bb = 0; bb < 4; ++bb) acc[p][bb] = 0.0;

    #pragma unroll 1
    for (int c = 0; c < 8; ++c) {
        #pragma unroll
        for (int it = 0; it < 4; ++it) {
            Xs[xk[it]+0][xb[it]] = xR[it].x; Xs[xk[it]+1][xb[it]] = xR[it].y;
            Xs[xk[it]+2][xb[it]] = xR[it].z; Xs[xk[it]+3][xb[it]] = xR[it].w;
        }
        #pragma unroll
        for (int it = 0; it < 2; ++it) {
            Ws[wk[it]+0][wq[it]] = wR[it].x; Ws[wk[it]+1][wq[it]] = wR[it].y;
            Ws[wk[it]+2][wq[it]] = wR[it].z; Ws[wk[it]+3][wq[it]] = wR[it].w;
        }
        __syncthreads();
        if (c < 7) {
            int k0 = (c + 1) * 32;
            #pragma unroll
            for (int it = 0; it < 4; ++it) xR[it] = *(const float4*)(xp[it] + k0);
            #pragma unroll
            for (int it = 0; it < 2; ++it) wR[it] = *(const float4*)(wp[it] + k0);
        }
        #pragma unroll 8
        for (int kk = 0; kk < 32; ++kk) {
            float4 xv = *(const float4*)&Xs[kk][b0];
            double2 w01 = *(const double2*)&Ws[kk][q0];
            double2 w23 = *(const double2*)&Ws[kk][q0 + 4];
            double xb0 = pk2(xv.x, xv.x), xb1 = pk2(xv.y, xv.y);
            double xb2 = pk2(xv.z, xv.z), xb3 = pk2(xv.w, xv.w);
            acc[0][0] = ffma2(w01.x, xb0, acc[0][0]);
            acc[0][1] = ffma2(w01.x, xb1, acc[0][1]);
            acc[0][2] = ffma2(w01.x, xb2, acc[0][2]);
            acc[0][3] = ffma2(w01.x, xb3, acc[0][3]);
            acc[1][0] = ffma2(w01.y, xb0, acc[1][0]);
            acc[1][1] = ffma2(w01.y, xb1, acc[1][1]);
            acc[1][2] = ffma2(w01.y, xb2, acc[1][2]);
            acc[1][3] = ffma2(w01.y, xb3, acc[1][3]);
            acc[2][0] = ffma2(w23.x, xb0, acc[2][0]);
            acc[2][1] = ffma2(w23.x, xb1, acc[2][1]);
            acc[2][2] = ffma2(w23.x, xb2, acc[2][2]);
            acc[2][3] = ffma2(w23.x, xb3, acc[2][3]);
            acc[3][0] = ffma2(w23.y, xb0, acc[3][0]);
            acc[3][1] = ffma2(w23.y, xb1, acc[3][1]);
            acc[3][2] = ffma2(w23.y, xb2, acc[3][2]);
            acc[3][3] = ffma2(w23.y, xb3, acc[3][3]);
        }
        __syncthreads();
    }
    size_t sbase = (size_t)s * PSTEP;
    #pragma unroll
    for (int p = 0; p < 4; ++p) {
        int qlo = qt * 64 + q0 + 2 * p;
        float blo = b_ih[qlo] + b_hh[qlo];
        float bhi = b_ih[qlo + 1] + b_hh[qlo + 1];
        float lo[4], hi[4];
        #pragma unroll
        for (int bb = 0; bb < 4; ++bb) unpk2(acc[p][bb], lo[bb], hi[bb]);
        float4 vlo = make_float4(lo[0] + blo, lo[1] + blo, lo[2] + blo, lo[3] + blo);
        float4 vhi = make_float4(hi[0] + bhi, hi[1] + bhi, hi[2] + bhi, hi[3] + bhi);
        *(float4*)&g_P[sbase + (size_t)qlo * BATCH + b0]       = vlo;
        *(float4*)&g_P[sbase + (size_t)(qlo + 1) * BATCH + b0] = vhi;
    }
}

// ---------------- persistent LSTM recurrence, fp16 2-pass, warp-decoupled ----------------
// 128 CTAs x 256 thr (8 warps). CTA ct: rows = 4 gates x dims [ct*8,ct*8+8).
// Warp w: batches [w*16,w*16+16), full K, private 4-stage ring, 16 chunks of K=64.
// z = Whi(fp16)·h(fp16) + Wlo(fp16)·h ; cell in-register.
#define PIT_A 1032
#define SM_A_HI 0
#define SM_A_LO 66048
#define SM_P    132096
#define SM_B    148480
#define SLICE_PITCH 144          /* bytes per B-slice row (64 fp16 + 8 pad) */
#define SLICE_STRIDE 2304        /* 16 rows x 144 B */
#define NSTG 4
#define STEP_SMEM (SM_B + 8 * NSTG * SLICE_STRIDE)   /* 222208 */

__global__ __launch_bounds__(256, 1) void step_persist(
        const float* __restrict__ W_hh, const float* __restrict__ c0) {
    extern __shared__ char smem[];
    uint32_t sb = smem_u32(smem);
    int tid = threadIdx.x, lane = tid & 31, wid = tid >> 5;
    int li = lane >> 3, l7 = lane & 7;
    int jd = lane >> 2, tc = lane & 3;
    int ct = blockIdx.x;

    __half* sAhi = (__half*)(smem + SM_A_HI);   // [32][1032]
    __half* sAlo = (__half*)(smem + SM_A_LO);
    float* Psm = (float*)(smem + SM_P);         // [32][128]

    // ---- load + split A once (fp16 hi/lo) ----
    {
        int lr = tid >> 3, seg = tid & 7;
        int gate = lr >> 3, jj = lr & 7;
        const float* src = W_hh + (size_t)(gate * HID + ct * 8 + jj) * HID + seg * 128;
        #pragma unroll 4
        for (int i = 0; i < 32; ++i) {
            float4 v = *(const float4*)(src + i * 4);
            int k = seg * 128 + i * 4;
            __half h0 = __float2half(v.x);
            __half h1 = __float2half(v.y);
            __half h2 = __float2half(v.z);
            __half h3 = __float2half(v.w);
            sAhi[lr * PIT_A + k + 0] = h0;
            sAhi[lr * PIT_A + k + 1] = h1;
            sAhi[lr * PIT_A + k + 2] = h2;
            sAhi[lr * PIT_A + k + 3] = h3;
            sAlo[lr * PIT_A + k + 0] = __float2half(v.x - __half2float(h0));
            sAlo[lr * PIT_A + k + 1] = __float2half(v.y - __half2float(h1));
            sAlo[lr * PIT_A + k + 2] = __float2half(v.z - __half2float(h2));
            sAlo[lr * PIT_A + k + 3] = __float2half(v.w - __half2float(h3));
        }
    }

    // ---- c-state in registers: (dim jd, batches wid*16 + n*8 + 2tc + e) ----
    float creg[2][2];
    {
        int d = ct * 8 + jd;
        #pragma unroll
        for (int n = 0; n < 2; ++n)
            #pragma unroll
            for (int e = 0; e < 2; ++e)
                creg[n][e] = c0[(size_t)(wid * 16 + n * 8 + 2 * tc + e) * HID + d];
    }

    // ---- ldmatrix A bases ----
    uint32_t aOff[2];
    #pragma unroll
    for (int mt = 0; mt < 2; ++mt) {
        int row = mt * 16 + (li & 1) * 8 + l7;
        aOff[mt] = sb + SM_A_HI + (uint32_t)row * (PIT_A * 2) + (li >> 1) * 16;
    }
    // B ldmatrix offset within slice (add ks*32)
    uint32_t bOff = (uint32_t)((li >> 1) * 8 + l7) * SLICE_PITCH + (li & 1) * 16;
    // B cp coords
    int brow[4], bseg[4];
    #pragma unroll
    for (int i = 0; i < 4; ++i) { int u = lane + i * 32; brow[i] = u >> 3; bseg[i] = u & 7; }
    // P loader coords
    int pq[4], ps[4];
    #pragma unroll
    for (int i = 0; i < 4; ++i) { int u = tid + i * 256; pq[i] = u >> 5; ps[i] = u & 31; }

    uint32_t myStage0 = sb + SM_B + (uint32_t)wid * NSTG * SLICE_STRIDE;

    __syncthreads();

    // prefetch P(0)
    {
        const float* Pg = g_P;
        #pragma unroll
        for (int i = 0; i < 4; ++i) {
            int qg = (pq[i] >> 3) * HID + ct * 8 + (pq[i] & 7);
            cp16(sb + SM_P + pq[i] * 512 + ps[i] * 16, Pg + (size_t)qg * BATCH + ps[i] * 4);
        }
        CP_COMMIT();
    }

    #pragma unroll 1
    for (int s = 0; s < SEQ; ++s) {
        const __half* h_in = g_h[s & 1];
        __half* h_out = g_h[(s + 1) & 1];

        // issue B chunks 0..2 into private ring
        #pragma unroll
        for (int cc = 0; cc < 3; ++cc) {
            #pragma unroll
            for (int i = 0; i < 4; ++i)
                cp16(myStage0 + cc * SLICE_STRIDE + brow[i] * SLICE_PITCH + bseg[i] * 16,
                     h_in + (size_t)(wid * 16 + brow[i]) * HID + cc * 64 + bseg[i] * 8);
            CP_COMMIT();
        }

        float acc[2][2][4];
        #pragma unroll
        for (int mt = 0; mt < 2; ++mt)
            #pragma unroll
            for (int n = 0; n < 2; ++n)
                #pragma unroll
                for (int e = 0; e < 4; ++e) acc[mt][n][e] = 0.0f;

        #pragma unroll 1
        for (int c = 0; c < 16; ++c) {
            if (c <= 13) { CP_WAIT(2); } else if (c == 14) { CP_WAIT(1); } else { CP_WAIT(0); }
            __syncwarp();
            if (c + 3 < 16) {
                int cn = c + 3;
                uint32_t dst = myStage0 + (cn & (NSTG - 1)) * SLICE_STRIDE;
                #pragma unroll
                for (int i = 0; i < 4; ++i)
                    cp16(dst + brow[i] * SLICE_PITCH + bseg[i] * 16,
                         h_in + (size_t)(wid * 16 + brow[i]) * HID + cn * 64 + bseg[i] * 8);
                CP_COMMIT();
            }
            uint32_t stBase = myStage0 + (c & (NSTG - 1)) * SLICE_STRIDE;
            uint32_t kByte = (uint32_t)c * 128;
            #pragma unroll
            for (int ks = 0; ks < 4; ++ks) {
                uint32_t b0, b1, b2, b3;
                ldm_x4(b0, b1, b2, b3, stBase + bOff + ks * 32);
                #pragma unroll
                for (int mt = 0; mt < 2; ++mt) {
                    uint32_t a0, a1, a2, a3;
                    ldm_x4(a0, a1, a2, a3, aOff[mt] + kByte + ks * 32);
                    mma16816(acc[mt][0], a0, a1, a2, a3, b0, b1);
                    mma16816(acc[mt][1], a0, a1, a2, a3, b2, b3);
                }
                #pragma unroll
                for (int mt = 0; mt < 2; ++mt) {
                    uint32_t a0, a1, a2, a3;
                    ldm_x4(a0, a1, a2, a3, aOff[mt] + 66048u + kByte + ks * 32);
                    mma16816(acc[mt][0], a0, a1, a2, a3, b0, b1);
                    mma16816(acc[mt][1], a0, a1, a2, a3, b2, b3);
                }
            }
        }

        // ---- LSTM cell in-register (i,f from mt0; g,o from mt1) ----
        {
            int d = ct * 8 + jd;
            bool last = (s == SEQ - 1);
            #pragma unroll
            for (int n = 0; n < 2; ++n) {
                int col = wid * 16 + n * 8 + 2 * tc;
                float2 pi = *(const float2*)&Psm[(0 * 8 + jd) * 128 + col];
                float2 pf = *(const float2*)&Psm[(1 * 8 + jd) * 128 + col];
                float2 pg = *(const float2*)&Psm[(2 * 8 + jd) * 128 + col];
                float2 po = *(const float2*)&Psm[(3 * 8 + jd) * 128 + col];
                #pragma unroll
                for (int e = 0; e < 2; ++e) {
                    float zi = acc[0][n][e]     + (e ? pi.y : pi.x);
                    float zf = acc[0][n][2 + e] + (e ? pf.y : pf.x);
                    float zg = acc[1][n][e]     + (e ? pg.y : pg.x);
                    float zo = acc[1][n][2 + e] + (e ? po.y : po.x);
                    float iv = sigf(zi), fv = sigf(zf), gv = tanhf(zg), ov = sigf(zo);
                    creg[n][e] = fv * creg[n][e] + iv * gv;
                    float hv = ov * tanhf(creg[n][e]);
                    size_t hidx = (size_t)(col + e) * HID + d;
                    h_out[hidx] = __float2half(hv);
                    if (last) g_hfin[hidx] = hv;
                }
            }
        }

        // ---- arrive ----
        __threadfence();
        __syncthreads();
        unsigned target = (unsigned)(s + 1);
        if (tid == 0) {
            unsigned old = atomicAdd(&g_bar, 1u);
            if (old == 128u * target - 1u) g_flag = target;
        }

        // ---- overlap: prefetch P(s+1) during the wait ----
        if (s + 1 < SEQ) {
            const float* Pg = g_P + (size_t)(s + 1) * PSTEP;
            #pragma unroll
            for (int i = 0; i < 4; ++i) {
                int qg = (pq[i] >> 3) * HID + ct * 8 + (pq[i] & 7);
                cp16(sb + SM_P + pq[i] * 512 + ps[i] * 16, Pg + (size_t)qg * BATCH + ps[i] * 4);
            }
            CP_COMMIT();
        }

        // ---- wait ----
        if (tid == 0) {
            while (g_flag < target) { }
            __threadfence();
        }
        __syncthreads();
    }
}

// ---------------- classifier ----------------
__global__ void out_kernel(const float* __restrict__ W_out,
                           const float* __restrict__ b_out,
                           float* __restrict__ out) {
    int c = blockIdx.x, b = blockIdx.y;
    const float* h = g_hfin + (size_t)b * HID;
    float sum = 0.0f;
    for (int d = threadIdx.x; d < HID; d += 128)
        sum += h[d] * W_out[c * HID + d];
    #pragma unroll
    for (int o = 16; o; o >>= 1) sum += __shfl_xor_sync(0xFFFFFFFFu, sum, o);
    __shared__ float red[4];
    if ((threadIdx.x & 31) == 0) red[threadIdx.x >> 5] = sum;
    __syncthreads();
    if (threadIdx.x == 0)
        out[b * NCLS + c] = red[0] + red[1] + red[2] + red[3] + b_out[c];
}

extern "C" void kernel_launch(void* const* d_in, const int* in_sizes, int n_in,
                              void* d_out, int out_size) {
    const float* x     = (const float*)d_in[0];
    const float* h0    = (const float*)d_in[1];
    const float* c0    = (const float*)d_in[2];
    const float* W_ih  = (const float*)d_in[3];
    const float* W_hh  = (const float*)d_in[4];
    const float* b_ih  = (const float*)d_in[5];
    const float* b_hh  = (const float*)d_in[6];
    const float* W_out = (const float*)d_in[7];
    const float* b_out = (const float*)d_in[8];
    float* out = (float*)d_out;

    cudaFuncSetAttribute(step_persist, cudaFuncAttributeMaxDynamicSharedMemorySize, STEP_SMEM);

    init_state<<<BATCH * HID / 256, 256>>>(h0);
    xproj_kernel<<<dim3(64, SEQ), 256>>>(x, W_ih, b_ih, b_hh);
    step_persist<<<128, 256, STEP_SMEM>>>(W_hh, c0);
    out_kernel<<<dim3(NCLS, BATCH), 128>>>(W_out, b_out, out);
}

// round 10
// speedup vs baseline: 2.7530x; 1.0029x over previous
#include <cuda_runtime.h>
#include <cuda_bf16.h>
#include <cuda_fp16.h>
#include <cstdint>
#include <math.h>

#define BATCH 128
#define SEQ   512
#define INDIM 256
#define HID   1024
#define NCLS  10
#define PSTEP (4 * HID * BATCH)

// ---------------- device globals ----------------
__device__ float g_P[(size_t)SEQ * PSTEP];   // [s][q(4096)][b(128)], q = gate*1024 + d
__device__ __align__(16) __half g_h[2][BATCH * HID];   // [b][d] fp16 state
__device__ float g_hfin[BATCH * HID];                  // final h fp32 for classifier
__device__ unsigned g_bar;
__device__ volatile unsigned g_flag;

__device__ __forceinline__ uint32_t smem_u32(const void* p) {
    uint32_t a;
    asm("{ .reg .u64 t; cvta.to.shared.u64 t, %1; cvt.u32.u64 %0, t; }" : "=r"(a) : "l"(p));
    return a;
}
__device__ __forceinline__ void cp16(uint32_t dst, const void* src) {
    asm volatile("cp.async.cg.shared.global [%0], [%1], 16;" :: "r"(dst), "l"(src));
}
#define CP_COMMIT() asm volatile("cp.async.commit_group;" ::: "memory")
#define CP_WAIT(n)  asm volatile("cp.async.wait_group %0;" :: "n"(n) : "memory")

__device__ __forceinline__ void ldm_x4(uint32_t &r0, uint32_t &r1, uint32_t &r2,
                                       uint32_t &r3, uint32_t addr) {
    asm volatile("ldmatrix.sync.aligned.m8n8.x4.shared.b16 {%0,%1,%2,%3}, [%4];"
        : "=r"(r0), "=r"(r1), "=r"(r2), "=r"(r3) : "r"(addr));
}
__device__ __forceinline__ void mma16816(float* c, uint32_t a0, uint32_t a1,
                                         uint32_t a2, uint32_t a3,
                                         uint32_t b0, uint32_t b1) {
    asm volatile(
        "mma.sync.aligned.m16n8k16.row.col.f32.f16.f16.f32 "
        "{%0,%1,%2,%3}, {%4,%5,%6,%7}, {%8,%9}, {%0,%1,%2,%3};"
        : "+f"(c[0]), "+f"(c[1]), "+f"(c[2]), "+f"(c[3])
        : "r"(a0), "r"(a1), "r"(a2), "r"(a3), "r"(b0), "r"(b1));
}
__device__ __forceinline__ float sigf(float x) { return 1.0f / (1.0f + __expf(-x)); }

// ---------------- init ----------------
__global__ void init_state(const float* __restrict__ h0) {
    int idx = blockIdx.x * 256 + threadIdx.x;   // over [b][d]
    if (idx == 0) { g_bar = 0; g_flag = 0; }
    g_h[0][idx] = __float2half(h0[idx]);
}

// ---------------- x projection (FFMA2, proven) ----------------
__device__ __forceinline__ double pk2(float x, float y) {
    double r; asm("mov.b64 %0, {%1, %2};" : "=d"(r) : "f"(x), "f"(y)); return r;
}
__device__ __forceinline__ void unpk2(double d, float &x, float &y) {
    asm("mov.b64 {%0, %1}, %2;" : "=f"(x), "=f"(y) : "d"(d));
}
__device__ __forceinline__ double ffma2(double a, double b, double c) {
    double r; asm("fma.rn.f32x2 %0, %1, %2, %3;" : "=d"(r) : "d"(a), "d"(b), "d"(c)); return r;
}

__global__ __launch_bounds__(256) void xproj_kernel(
        const float* __restrict__ x, const float* __restrict__ W_ih,
        const float* __restrict__ b_ih, const float* __restrict__ b_hh) {
    __shared__ float Xs[32][132];
    __shared__ float Ws[32][68];
    int tid = threadIdx.x, lane = tid & 31, w = tid >> 5;
    int qt = blockIdx.x, s = blockIdx.y;
    int q0 = w * 8, b0 = lane * 4;

    int xb[4], xk[4]; const float* xp[4];
    #pragma unroll
    for (int it = 0; it < 4; ++it) {
        int f = tid + it * 256;
        xb[it] = f >> 3; xk[it] = (f & 7) * 4;
        xp[it] = x + (size_t)xb[it] * (SEQ * INDIM) + s * INDIM + xk[it];
    }
    int wq[2], wk[2]; const float* wp[2];
    #pragma unroll
    for (int it = 0; it < 2; ++it) {
        int f = tid + it * 256;
        wq[it] = f >> 3; wk[it] = (f & 7) * 4;
        wp[it] = W_ih + (size_t)(qt * 64 + wq[it]) * INDIM + wk[it];
    }
    float4 xR[4], wR[2];
    #pragma unroll
    for (int it = 0; it < 4; ++it) xR[it] = *(const float4*)xp[it];
    #pragma unroll
    for (int it = 0; it < 2; ++it) wR[it] = *(const float4*)wp[it];

    double acc[4][4];
    #pragma unroll
    for (int p = 0; p < 4; ++p)
        #pragma unroll
        for (int bb = 0; bb < 4; ++bb) acc[p][bb] = 0.0;

    #pragma unroll 1
    for (int c = 0; c < 8; ++c) {
        #pragma unroll
        for (int it = 0; it < 4; ++it) {
            Xs[xk[it]+0][xb[it]] = xR[it].x; Xs[xk[it]+1][xb[it]] = xR[it].y;
            Xs[xk[it]+2][xb[it]] = xR[it].z; Xs[xk[it]+3][xb[it]] = xR[it].w;
        }
        #pragma unroll
        for (int it = 0; it < 2; ++it) {
            Ws[wk[it]+0][wq[it]] = wR[it].x; Ws[wk[it]+1][wq[it]] = wR[it].y;
            Ws[wk[it]+2][wq[it]] = wR[it].z; Ws[wk[it]+3][wq[it]] = wR[it].w;
        }
        __syncthreads();
        if (c < 7) {
            int k0 = (c + 1) * 32;
            #pragma unroll
            for (int it = 0; it < 4; ++it) xR[it] = *(const float4*)(xp[it] + k0);
            #pragma unroll
            for (int it = 0; it < 2; ++it) wR[it] = *(const float4*)(wp[it] + k0);
        }
        #pragma unroll 8
        for (int kk = 0; kk < 32; ++kk) {
            float4 xv = *(const float4*)&Xs[kk][b0];
            double2 w01 = *(const double2*)&Ws[kk][q0];
            double2 w23 = *(const double2*)&Ws[kk][q0 + 4];
            double xb0 = pk2(xv.x, xv.x), xb1 = pk2(xv.y, xv.y);
            double xb2 = pk2(xv.z, xv.z), xb3 = pk2(xv.w, xv.w);
            acc[0][0] = ffma2(w01.x, xb0, acc[0][0]);
            acc[0][1] = ffma2(w01.x, xb1, acc[0][1]);
            acc[0][2] = ffma2(w01.x, xb2, acc[0][2]);
            acc[0][3] = ffma2(w01.x, xb3, acc[0][3]);
            acc[1][0] = ffma2(w01.y, xb0, acc[1][0]);
            acc[1][1] = ffma2(w01.y, xb1, acc[1][1]);
            acc[1][2] = ffma2(w01.y, xb2, acc[1][2]);
            acc[1][3] = ffma2(w01.y, xb3, acc[1][3]);
            acc[2][0] = ffma2(w23.x, xb0, acc[2][0]);
            acc[2][1] = ffma2(w23.x, xb1, acc[2][1]);
            acc[2][2] = ffma2(w23.x, xb2, acc[2][2]);
            acc[2][3] = ffma2(w23.x, xb3, acc[2][3]);
            acc[3][0] = ffma2(w23.y, xb0, acc[3][0]);
            acc[3][1] = ffma2(w23.y, xb1, acc[3][1]);
            acc[3][2] = ffma2(w23.y, xb2, acc[3][2]);
            acc[3][3] = ffma2(w23.y, xb3, acc[3][3]);
        }
        __syncthreads();
    }
    size_t sbase = (size_t)s * PSTEP;
    #pragma unroll
    for (int p = 0; p < 4; ++p) {
        int qlo = qt * 64 + q0 + 2 * p;
        float blo = b_ih[qlo] + b_hh[qlo];
        float bhi = b_ih[qlo + 1] + b_hh[qlo + 1];
        float lo[4], hi[4];
        #pragma unroll
        for (int bb = 0; bb < 4; ++bb) unpk2(acc[p][bb], lo[bb], hi[bb]);
        float4 vlo = make_float4(lo[0] + blo, lo[1] + blo, lo[2] + blo, lo[3] + blo);
        float4 vhi = make_float4(hi[0] + bhi, hi[1] + bhi, hi[2] + bhi, hi[3] + bhi);
        *(float4*)&g_P[sbase + (size_t)qlo * BATCH + b0]       = vlo;
        *(float4*)&g_P[sbase + (size_t)(qlo + 1) * BATCH + b0] = vhi;
    }
}

// ---------------- persistent LSTM recurrence, fp16 2-pass, warp-decoupled ----------------
// 128 CTAs x 256 thr (8 warps). CTA ct: rows = 4 gates x dims [ct*8,ct*8+8).
// Warp w: batches [w*16,w*16+16), full K, private 4-stage ring, 16 chunks of K=64.
// z = Whi(fp16)·h(fp16) + Wlo(fp16)·h ; cell in-register.
#define PIT_A 1032
#define SM_A_HI 0
#define SM_A_LO 66048
#define SM_P    132096
#define SM_B    148480
#define SLICE_PITCH 144          /* bytes per B-slice row (64 fp16 + 8 pad) */
#define SLICE_STRIDE 2304        /* 16 rows x 144 B */
#define NSTG 4
#define STEP_SMEM (SM_B + 8 * NSTG * SLICE_STRIDE)   /* 222208 */

__global__ __launch_bounds__(256, 1) void step_persist(
        const float* __restrict__ W_hh, const float* __restrict__ c0) {
    extern __shared__ char smem[];
    uint32_t sb = smem_u32(smem);
    int tid = threadIdx.x, lane = tid & 31, wid = tid >> 5;
    int li = lane >> 3, l7 = lane & 7;
    int jd = lane >> 2, tc = lane & 3;
    int ct = blockIdx.x;

    __half* sAhi = (__half*)(smem + SM_A_HI);   // [32][1032]
    __half* sAlo = (__half*)(smem + SM_A_LO);
    float* Psm = (float*)(smem + SM_P);         // [32][128]

    // ---- load + split A once (fp16 hi/lo) ----
    {
        int lr = tid >> 3, seg = tid & 7;
        int gate = lr >> 3, jj = lr & 7;
        const float* src = W_hh + (size_t)(gate * HID + ct * 8 + jj) * HID + seg * 128;
        #pragma unroll 4
        for (int i = 0; i < 32; ++i) {
            float4 v = *(const float4*)(src + i * 4);
            int k = seg * 128 + i * 4;
            __half h0 = __float2half(v.x);
            __half h1 = __float2half(v.y);
            __half h2 = __float2half(v.z);
            __half h3 = __float2half(v.w);
            sAhi[lr * PIT_A + k + 0] = h0;
            sAhi[lr * PIT_A + k + 1] = h1;
            sAhi[lr * PIT_A + k + 2] = h2;
            sAhi[lr * PIT_A + k + 3] = h3;
            sAlo[lr * PIT_A + k + 0] = __float2half(v.x - __half2float(h0));
            sAlo[lr * PIT_A + k + 1] = __float2half(v.y - __half2float(h1));
            sAlo[lr * PIT_A + k + 2] = __float2half(v.z - __half2float(h2));
            sAlo[lr * PIT_A + k + 3] = __float2half(v.w - __half2float(h3));
        }
    }

    // ---- c-state in registers: (dim jd, batches wid*16 + n*8 + 2tc + e) ----
    float creg[2][2];
    {
        int d = ct * 8 + jd;
        #pragma unroll
        for (int n = 0; n < 2; ++n)
            #pragma unroll
            for (int e = 0; e < 2; ++e)
                creg[n][e] = c0[(size_t)(wid * 16 + n * 8 + 2 * tc + e) * HID + d];
    }

    // ---- ldmatrix A bases ----
    uint32_t aOff[2];
    #pragma unroll
    for (int mt = 0; mt < 2; ++mt) {
        int row = mt * 16 + (li & 1) * 8 + l7;
        aOff[mt] = sb + SM_A_HI + (uint32_t)row * (PIT_A * 2) + (li >> 1) * 16;
    }
    // B ldmatrix offset within slice (add ks*32)
    uint32_t bOff = (uint32_t)((li >> 1) * 8 + l7) * SLICE_PITCH + (li & 1) * 16;
    // B cp coords
    int brow[4], bseg[4];
    #pragma unroll
    for (int i = 0; i < 4; ++i) { int u = lane + i * 32; brow[i] = u >> 3; bseg[i] = u & 7; }
    // P loader coords
    int pq[4], ps[4];
    #pragma unroll
    for (int i = 0; i < 4; ++i) { int u = tid + i * 256; pq[i] = u >> 5; ps[i] = u & 31; }

    uint32_t myStage0 = sb + SM_B + (uint32_t)wid * NSTG * SLICE_STRIDE;

    __syncthreads();

    // prefetch P(0)
    {
        const float* Pg = g_P;
        #pragma unroll
        for (int i = 0; i < 4; ++i) {
            int qg = (pq[i] >> 3) * HID + ct * 8 + (pq[i] & 7);
            cp16(sb + SM_P + pq[i] * 512 + ps[i] * 16, Pg + (size_t)qg * BATCH + ps[i] * 4);
        }
        CP_COMMIT();
    }

    #pragma unroll 1
    for (int s = 0; s < SEQ; ++s) {
        const __half* h_in = g_h[s & 1];
        __half* h_out = g_h[(s + 1) & 1];

        // issue B chunks 0..2 into private ring
        #pragma unroll
        for (int cc = 0; cc < 3; ++cc) {
            #pragma unroll
            for (int i = 0; i < 4; ++i)
                cp16(myStage0 + cc * SLICE_STRIDE + brow[i] * SLICE_PITCH + bseg[i] * 16,
                     h_in + (size_t)(wid * 16 + brow[i]) * HID + cc * 64 + bseg[i] * 8);
            CP_COMMIT();
        }

        float acc[2][2][4];
        #pragma unroll
        for (int mt = 0; mt < 2; ++mt)
            #pragma unroll
            for (int n = 0; n < 2; ++n)
                #pragma unroll
                for (int e = 0; e < 4; ++e) acc[mt][n][e] = 0.0f;

        #pragma unroll 1
        for (int c = 0; c < 16; ++c) {
            if (c <= 13) { CP_WAIT(2); } else if (c == 14) { CP_WAIT(1); } else { CP_WAIT(0); }
            __syncwarp();
            if (c + 3 < 16) {
                int cn = c + 3;
                uint32_t dst = myStage0 + (cn & (NSTG - 1)) * SLICE_STRIDE;
                #pragma unroll
                for (int i = 0; i < 4; ++i)
                    cp16(dst + brow[i] * SLICE_PITCH + bseg[i] * 16,
                         h_in + (size_t)(wid * 16 + brow[i]) * HID + cn * 64 + bseg[i] * 8);
                CP_COMMIT();
            }
            uint32_t stBase = myStage0 + (c & (NSTG - 1)) * SLICE_STRIDE;
            uint32_t kByte = (uint32_t)c * 128;
            #pragma unroll
            for (int ks = 0; ks < 4; ++ks) {
                uint32_t b0, b1, b2, b3;
                ldm_x4(b0, b1, b2, b3, stBase + bOff + ks * 32);
                #pragma unroll
                for (int mt = 0; mt < 2; ++mt) {
                    uint32_t a0, a1, a2, a3;
                    ldm_x4(a0, a1, a2, a3, aOff[mt] + kByte + ks * 32);
                    mma16816(acc[mt][0], a0, a1, a2, a3, b0, b1);
                    mma16816(acc[mt][1], a0, a1, a2, a3, b2, b3);
                }
                #pragma unroll
                for (int mt = 0; mt < 2; ++mt) {
                    uint32_t a0, a1, a2, a3;
                    ldm_x4(a0, a1, a2, a3, aOff[mt] + 66048u + kByte + ks * 32);
                    mma16816(acc[mt][0], a0, a1, a2, a3, b0, b1);
                    mma16816(acc[mt][1], a0, a1, a2, a3, b2, b3);
                }
            }
        }

        // ---- LSTM cell in-register (i,f from mt0; g,o from mt1) ----
        {
            int d = ct * 8 + jd;
            bool last = (s == SEQ - 1);
            #pragma unroll
            for (int n = 0; n < 2; ++n) {
                int col = wid * 16 + n * 8 + 2 * tc;
                float2 pi = *(const float2*)&Psm[(0 * 8 + jd) * 128 + col];
                float2 pf = *(const float2*)&Psm[(1 * 8 + jd) * 128 + col];
                float2 pg = *(const float2*)&Psm[(2 * 8 + jd) * 128 + col];
                float2 po = *(const float2*)&Psm[(3 * 8 + jd) * 128 + col];
                #pragma unroll
                for (int e = 0; e < 2; ++e) {
                    float zi = acc[0][n][e]     + (e ? pi.y : pi.x);
                    float zf = acc[0][n][2 + e] + (e ? pf.y : pf.x);
                    float zg = acc[1][n][e]     + (e ? pg.y : pg.x);
                    float zo = acc[1][n][2 + e] + (e ? po.y : po.x);
                    float iv = sigf(zi), fv = sigf(zf), gv = tanhf(zg), ov = sigf(zo);
                    creg[n][e] = fv * creg[n][e] + iv * gv;
                    float hv = ov * tanhf(creg[n][e]);
                    size_t hidx = (size_t)(col + e) * HID + d;
                    h_out[hidx] = __float2half(hv);
                    if (last) g_hfin[hidx] = hv;
                }
            }
        }

        // ---- arrive ----
        __threadfence();
        __syncthreads();
        unsigned target = (unsigned)(s + 1);
        if (tid == 0) {
            unsigned old = atomicAdd(&g_bar, 1u);
            if (old == 128u * target - 1u) g_flag = target;
        }

        // ---- overlap: prefetch P(s+1) during the wait ----
        if (s + 1 < SEQ) {
            const float* Pg = g_P + (size_t)(s + 1) * PSTEP;
            #pragma unroll
            for (int i = 0; i < 4; ++i) {
                int qg = (pq[i] >> 3) * HID + ct * 8 + (pq[i] & 7);
                cp16(sb + SM_P + pq[i] * 512 + ps[i] * 16, Pg + (size_t)qg * BATCH + ps[i] * 4);
            }
            CP_COMMIT();
        }

        // ---- wait ----
        if (tid == 0) {
            while (g_flag < target) { }
            __threadfence();
        }
        __syncthreads();
    }
}

// ---------------- classifier ----------------
__global__ void out_kernel(const float* __restrict__ W_out,
                           const float* __restrict__ b_out,
                           float* __restrict__ out) {
    int c = blockIdx.x, b = blockIdx.y;
    const float* h = g_hfin + (size_t)b * HID;
    float sum = 0.0f;
    for (int d = threadIdx.x; d < HID; d += 128)
        sum += h[d] * W_out[c * HID + d];
    #pragma unroll
    for (int o = 16; o; o >>= 1) sum += __shfl_xor_sync(0xFFFFFFFFu, sum, o);
    __shared__ float red[4];
    if ((threadIdx.x & 31) == 0) red[threadIdx.x >> 5] = sum;
    __syncthreads();
    if (threadIdx.x == 0)
        out[b * NCLS + c] = red[0] + red[1] + red[2] + red[3] + b_out[c];
}

extern "C" void kernel_launch(void* const* d_in, const int* in_sizes, int n_in,
                              void* d_out, int out_size) {
    const float* x     = (const float*)d_in[0];
    const float* h0    = (const float*)d_in[1];
    const float* c0    = (const float*)d_in[2];
    const float* W_ih  = (const float*)d_in[3];
    const float* W_hh  = (const float*)d_in[4];
    const float* b_ih  = (const float*)d_in[5];
    const float* b_hh  = (const float*)d_in[6];
    const float* W_out = (const float*)d_in[7];
    const float* b_out = (const float*)d_in[8];
    float* out = (float*)d_out;

    cudaFuncSetAttribute(step_persist, cudaFuncAttributeMaxDynamicSharedMemorySize, STEP_SMEM);

    init_state<<<BATCH * HID / 256, 256>>>(h0);
    xproj_kernel<<<dim3(64, SEQ), 256>>>(x, W_ih, b_ih, b_hh);
    step_persist<<<128, 256, STEP_SMEM>>>(W_hh, c0);
    out_kernel<<<dim3(NCLS, BATCH), 128>>>(W_out, b_out, out);
}

// round 11
// speedup vs baseline: 4.1023x; 1.4901x over previous
#include <cuda_runtime.h>
#include <cuda_fp16.h>
#include <cstdint>
#include <math.h>

#define BATCH 128
#define SEQ   512
#define INDIM 256
#define HID   1024
#define NCLS  10
#define PSTEP (4 * HID * BATCH)

// ---------------- device globals ----------------
__device__ float g_P[(size_t)SEQ * PSTEP];   // [s][q(4096)][b(128)]
__device__ __align__(16) __half g_xh[(size_t)BATCH * SEQ * INDIM];  // x fp16 [b][s][k]
__device__ __align__(16) __half g_Wihi[4096 * INDIM];   // W_ih hi fp16
__device__ __align__(16) __half g_Wilo[4096 * INDIM];   // W_ih lo fp16
__device__ __align__(16) __half g_h[2][BATCH * HID];    // [b][d] fp16 state
__device__ float g_hfin[BATCH * HID];
__device__ unsigned g_bar;
__device__ volatile unsigned g_flag;

__device__ __forceinline__ uint32_t smem_u32(const void* p) {
    uint32_t a;
    asm("{ .reg .u64 t; cvta.to.shared.u64 t, %1; cvt.u32.u64 %0, t; }" : "=r"(a) : "l"(p));
    return a;
}
__device__ __forceinline__ void cp16(uint32_t dst, const void* src) {
    asm volatile("cp.async.cg.shared.global [%0], [%1], 16;" :: "r"(dst), "l"(src));
}
#define CP_COMMIT() asm volatile("cp.async.commit_group;" ::: "memory")
#define CP_WAIT(n)  asm volatile("cp.async.wait_group %0;" :: "n"(n) : "memory")

__device__ __forceinline__ void ldm_x4(uint32_t &r0, uint32_t &r1, uint32_t &r2,
                                       uint32_t &r3, uint32_t addr) {
    asm volatile("ldmatrix.sync.aligned.m8n8.x4.shared.b16 {%0,%1,%2,%3}, [%4];"
        : "=r"(r0), "=r"(r1), "=r"(r2), "=r"(r3) : "r"(addr));
}
__device__ __forceinline__ void mma16816(float* c, uint32_t a0, uint32_t a1,
                                         uint32_t a2, uint32_t a3,
                                         uint32_t b0, uint32_t b1) {
    asm volatile(
        "mma.sync.aligned.m16n8k16.row.col.f32.f16.f16.f32 "
        "{%0,%1,%2,%3}, {%4,%5,%6,%7}, {%8,%9}, {%0,%1,%2,%3};"
        : "+f"(c[0]), "+f"(c[1]), "+f"(c[2]), "+f"(c[3])
        : "r"(a0), "r"(a1), "r"(a2), "r"(a3), "r"(b0), "r"(b1));
}
__device__ __forceinline__ float sigf(float x) { return 1.0f / (1.0f + __expf(-x)); }

// ---------------- pre-kernels ----------------
__global__ void init_state(const float* __restrict__ h0) {
    int idx = blockIdx.x * 256 + threadIdx.x;
    if (idx == 0) { g_bar = 0; g_flag = 0; }
    g_h[0][idx] = __float2half(h0[idx]);
}
__global__ void cvt_x(const float* __restrict__ x) {
    size_t idx = (size_t)blockIdx.x * 256 + threadIdx.x;
    g_xh[idx] = __float2half(x[idx]);
}
__global__ void split_Wih(const float* __restrict__ W_ih) {
    int idx = blockIdx.x * 256 + threadIdx.x;   // over 4096*256
    float w = W_ih[idx];
    __half hi = __float2half(w);
    g_Wihi[idx] = hi;
    g_Wilo[idx] = __float2half(w - __half2float(hi));
}

// ---------------- xproj via mma.sync (fp16, W split 2-pass) ----------------
// grid (64 qt, 512 s), 256 thr. CTA: P[s][qt*64..+64][0..128].
// warp: qh = wid>>2 (32 q), bq = wid&3 (32 b).
#define XP_PIT_A 264                       /* fp16 pitch (256+8) */
#define XP_A_SZ  (64 * XP_PIT_A * 2)       /* 33792 B */
#define XP_PIT_B 72
#define XP_B_SZ  (128 * XP_PIT_B * 2)      /* 18432 B */
#define XP_SM_AHI 0
#define XP_SM_ALO XP_A_SZ
#define XP_SM_BIAS (2 * XP_A_SZ)           /* 67584, 64 floats */
#define XP_SM_B   (XP_SM_BIAS + 256)       /* 67840 */
#define XP_SMEM   (XP_SM_B + 3 * XP_B_SZ)  /* 123136 */

__global__ __launch_bounds__(256, 1) void xproj_mma(
        const float* __restrict__ b_ih, const float* __restrict__ b_hh) {
    extern __shared__ char smem[];
    uint32_t sb = smem_u32(smem);
    int tid = threadIdx.x, lane = tid & 31, wid = tid >> 5;
    int li = lane >> 3, l7 = lane & 7;
    int qt = blockIdx.x, s = blockIdx.y;
    int qh = wid >> 2, bq = wid & 3;
    int q0 = qh * 32, b0 = bq * 32;

    float* bias = (float*)(smem + XP_SM_BIAS);
    if (tid < 64) {
        int q = qt * 64 + tid;
        bias[tid] = b_ih[q] + b_hh[q];
    }

    // A one-time load (hi+lo): 8 cp16/thread each
    {
        #pragma unroll
        for (int i = 0; i < 8; ++i) {
            int idx = tid + i * 256;
            int row = idx >> 5, seg = idx & 31;
            const __half* src = g_Wihi + (size_t)(qt * 64 + row) * INDIM + seg * 8;
            cp16(sb + XP_SM_AHI + row * (XP_PIT_A * 2) + seg * 16, src);
        }
        #pragma unroll
        for (int i = 0; i < 8; ++i) {
            int idx = tid + i * 256;
            int row = idx >> 5, seg = idx & 31;
            const __half* src = g_Wilo + (size_t)(qt * 64 + row) * INDIM + seg * 8;
            cp16(sb + XP_SM_ALO + row * (XP_PIT_A * 2) + seg * 16, src);
        }
    }
    // B loader coords (4 cp16/thread per chunk of k=64)
    int brow[4], bseg[4];
    #pragma unroll
    for (int i = 0; i < 4; ++i) { int u = tid + i * 256; brow[i] = u >> 3; bseg[i] = u & 7; }

    auto issueB = [&](int c, int st) {
        uint32_t dst = sb + XP_SM_B + st * XP_B_SZ;
        #pragma unroll
        for (int i = 0; i < 4; ++i)
            cp16(dst + brow[i] * (XP_PIT_B * 2) + bseg[i] * 16,
                 g_xh + (size_t)brow[i] * (SEQ * INDIM) + (size_t)s * INDIM + c * 64 + bseg[i] * 8);
        CP_COMMIT();
    };
    issueB(0, 0);   // group also covers A cps
    issueB(1, 1);

    // ldmatrix bases
    uint32_t aOff[2];
    #pragma unroll
    for (int mt = 0; mt < 2; ++mt) {
        int row = q0 + mt * 16 + (li & 1) * 8 + l7;
        aOff[mt] = sb + XP_SM_AHI + (uint32_t)row * (XP_PIT_A * 2) + (li >> 1) * 16;
    }
    uint32_t bOff[2];
    #pragma unroll
    for (int p = 0; p < 2; ++p) {
        int row = b0 + p * 16 + (li >> 1) * 8 + l7;
        bOff[p] = (uint32_t)row * (XP_PIT_B * 2) + (li & 1) * 16;
    }

    float acc[2][4][4];
    #pragma unroll
    for (int mt = 0; mt < 2; ++mt)
        #pragma unroll
        for (int n = 0; n < 4; ++n)
            #pragma unroll
            for (int e = 0; e < 4; ++e) acc[mt][n][e] = 0.0f;

    #pragma unroll 1
    for (int c = 0; c < 4; ++c) {
        if (c == 3) { CP_WAIT(0); } else { CP_WAIT(1); }
        __syncthreads();
        if (c + 2 < 4) issueB(c + 2, (c + 2) % 3);
        uint32_t stBase = sb + XP_SM_B + (c % 3) * XP_B_SZ;
        uint32_t kByte = (uint32_t)c * 128;
        #pragma unroll
        for (int ks = 0; ks < 4; ++ks) {
            uint32_t bfr[4][2];
            #pragma unroll
            for (int p = 0; p < 2; ++p)
                ldm_x4(bfr[2*p][0], bfr[2*p][1], bfr[2*p+1][0], bfr[2*p+1][1],
                       stBase + bOff[p] + ks * 32);
            #pragma unroll
            for (int mt = 0; mt < 2; ++mt) {
                uint32_t a0, a1, a2, a3;
                ldm_x4(a0, a1, a2, a3, aOff[mt] + kByte + ks * 32);
                #pragma unroll
                for (int n = 0; n < 4; ++n)
                    mma16816(acc[mt][n], a0, a1, a2, a3, bfr[n][0], bfr[n][1]);
            }
            #pragma unroll
            for (int mt = 0; mt < 2; ++mt) {
                uint32_t a0, a1, a2, a3;
                ldm_x4(a0, a1, a2, a3, aOff[mt] + (uint32_t)XP_A_SZ + kByte + ks * 32);
                #pragma unroll
                for (int n = 0; n < 4; ++n)
                    mma16816(acc[mt][n], a0, a1, a2, a3, bfr[n][0], bfr[n][1]);
            }
        }
        __syncthreads();
    }

    // epilogue: bias + store to g_P[s][q][b]
    size_t sbase = (size_t)s * PSTEP;
    #pragma unroll
    for (int mt = 0; mt < 2; ++mt) {
        #pragma unroll
        for (int n = 0; n < 4; ++n) {
            int rl0 = q0 + mt * 16 + (lane >> 2);
            int col = b0 + n * 8 + (lane & 3) * 2;
            int q0g = qt * 64 + rl0;
            float bv0 = bias[rl0], bv1 = bias[rl0 + 8];
            *(float2*)&g_P[sbase + (size_t)q0g * BATCH + col] =
                make_float2(acc[mt][n][0] + bv0, acc[mt][n][1] + bv0);
            *(float2*)&g_P[sbase + (size_t)(q0g + 8) * BATCH + col] =
                make_float2(acc[mt][n][2] + bv1, acc[mt][n][3] + bv1);
        }
    }
}

// ---------------- persistent LSTM recurrence, fp16 single-pass ----------------
#define PIT_A 1032
#define SM_A  0
#define SM_P  66048
#define SM_B  82432
#define SLICE_PITCH 144
#define SLICE_STRIDE 2304
#define NSTG 4
#define STEP_SMEM (SM_B + 8 * NSTG * SLICE_STRIDE)   /* 156160 */

__global__ __launch_bounds__(256, 1) void step_persist(
        const float* __restrict__ W_hh, const float* __restrict__ c0) {
    extern __shared__ char smem[];
    uint32_t sb = smem_u32(smem);
    int tid = threadIdx.x, lane = tid & 31, wid = tid >> 5;
    int li = lane >> 3, l7 = lane & 7;
    int jd = lane >> 2, tc = lane & 3;
    int ct = blockIdx.x;

    __half* sA = (__half*)(smem + SM_A);   // [32][1032]
    float* Psm = (float*)(smem + SM_P);    // [32][128]

    // ---- load A once (fp16 single) ----
    {
        int lr = tid >> 3, seg = tid & 7;
        int gate = lr >> 3, jj = lr & 7;
        const float* src = W_hh + (size_t)(gate * HID + ct * 8 + jj) * HID + seg * 128;
        #pragma unroll 4
        for (int i = 0; i < 32; ++i) {
            float4 v = *(const float4*)(src + i * 4);
            int k = seg * 128 + i * 4;
            sA[lr * PIT_A + k + 0] = __float2half(v.x);
            sA[lr * PIT_A + k + 1] = __float2half(v.y);
            sA[lr * PIT_A + k + 2] = __float2half(v.z);
            sA[lr * PIT_A + k + 3] = __float2half(v.w);
        }
    }

    // ---- c-state in registers ----
    float creg[2][2];
    {
        int d = ct * 8 + jd;
        #pragma unroll
        for (int n = 0; n < 2; ++n)
            #pragma unroll
            for (int e = 0; e < 2; ++e)
                creg[n][e] = c0[(size_t)(wid * 16 + n * 8 + 2 * tc + e) * HID + d];
    }

    uint32_t aOff[2];
    #pragma unroll
    for (int mt = 0; mt < 2; ++mt) {
        int row = mt * 16 + (li & 1) * 8 + l7;
        aOff[mt] = sb + SM_A + (uint32_t)row * (PIT_A * 2) + (li >> 1) * 16;
    }
    uint32_t bOff = (uint32_t)((li >> 1) * 8 + l7) * SLICE_PITCH + (li & 1) * 16;
    int brow[4], bseg[4];
    #pragma unroll
    for (int i = 0; i < 4; ++i) { int u = lane + i * 32; brow[i] = u >> 3; bseg[i] = u & 7; }
    int pq[4], ps[4];
    #pragma unroll
    for (int i = 0; i < 4; ++i) { int u = tid + i * 256; pq[i] = u >> 5; ps[i] = u & 31; }

    uint32_t myStage0 = sb + SM_B + (uint32_t)wid * NSTG * SLICE_STRIDE;

    __syncthreads();

    // prefetch P(0)
    {
        #pragma unroll
        for (int i = 0; i < 4; ++i) {
            int qg = (pq[i] >> 3) * HID + ct * 8 + (pq[i] & 7);
            cp16(sb + SM_P + pq[i] * 512 + ps[i] * 16, g_P + (size_t)qg * BATCH + ps[i] * 4);
        }
        CP_COMMIT();
    }

    #pragma unroll 1
    for (int s = 0; s < SEQ; ++s) {
        const __half* h_in = g_h[s & 1];
        __half* h_out = g_h[(s + 1) & 1];

        #pragma unroll
        for (int cc = 0; cc < 3; ++cc) {
            #pragma unroll
            for (int i = 0; i < 4; ++i)
                cp16(myStage0 + cc * SLICE_STRIDE + brow[i] * SLICE_PITCH + bseg[i] * 16,
                     h_in + (size_t)(wid * 16 + brow[i]) * HID + cc * 64 + bseg[i] * 8);
            CP_COMMIT();
        }

        float acc[2][2][4];
        #pragma unroll
        for (int mt = 0; mt < 2; ++mt)
            #pragma unroll
            for (int n = 0; n < 2; ++n)
                #pragma unroll
                for (int e = 0; e < 4; ++e) acc[mt][n][e] = 0.0f;

        #pragma unroll 1
        for (int c = 0; c < 16; ++c) {
            if (c <= 13) { CP_WAIT(2); } else if (c == 14) { CP_WAIT(1); } else { CP_WAIT(0); }
            __syncwarp();
            if (c + 3 < 16) {
                int cn = c + 3;
                uint32_t dst = myStage0 + (cn & (NSTG - 1)) * SLICE_STRIDE;
                #pragma unroll
                for (int i = 0; i < 4; ++i)
                    cp16(dst + brow[i] * SLICE_PITCH + bseg[i] * 16,
                         h_in + (size_t)(wid * 16 + brow[i]) * HID + cn * 64 + bseg[i] * 8);
                CP_COMMIT();
            }
            uint32_t stBase = myStage0 + (c & (NSTG - 1)) * SLICE_STRIDE;
            uint32_t kByte = (uint32_t)c * 128;
            #pragma unroll
            for (int ks = 0; ks < 4; ++ks) {
                uint32_t b0, b1, b2, b3;
                ldm_x4(b0, b1, b2, b3, stBase + bOff + ks * 32);
                #pragma unroll
                for (int mt = 0; mt < 2; ++mt) {
                    uint32_t a0, a1, a2, a3;
                    ldm_x4(a0, a1, a2, a3, aOff[mt] + kByte + ks * 32);
                    mma16816(acc[mt][0], a0, a1, a2, a3, b0, b1);
                    mma16816(acc[mt][1], a0, a1, a2, a3, b2, b3);
                }
            }
        }

        // ---- LSTM cell in-register ----
        {
            int d = ct * 8 + jd;
            bool last = (s == SEQ - 1);
            #pragma unroll
            for (int n = 0; n < 2; ++n) {
                int col = wid * 16 + n * 8 + 2 * tc;
                float2 pi = *(const float2*)&Psm[(0 * 8 + jd) * 128 + col];
                float2 pf = *(const float2*)&Psm[(1 * 8 + jd) * 128 + col];
                float2 pg = *(const float2*)&Psm[(2 * 8 + jd) * 128 + col];
                float2 po = *(const float2*)&Psm[(3 * 8 + jd) * 128 + col];
                #pragma unroll
                for (int e = 0; e < 2; ++e) {
                    float zi = acc[0][n][e]     + (e ? pi.y : pi.x);
                    float zf = acc[0][n][2 + e] + (e ? pf.y : pf.x);
                    float zg = acc[1][n][e]     + (e ? pg.y : pg.x);
                    float zo = acc[1][n][2 + e] + (e ? po.y : po.x);
                    float iv = sigf(zi), fv = sigf(zf), gv = tanhf(zg), ov = sigf(zo);
                    creg[n][e] = fv * creg[n][e] + iv * gv;
                    float hv = ov * tanhf(creg[n][e]);
                    size_t hidx = (size_t)(col + e) * HID + d;
                    h_out[hidx] = __float2half(hv);
                    if (last) g_hfin[hidx] = hv;
                }
            }
        }

        // ---- arrive / overlap P prefetch / wait ----
        __threadfence();
        __syncthreads();
        unsigned target = (unsigned)(s + 1);
        if (tid == 0) {
            unsigned old = atomicAdd(&g_bar, 1u);
            if (old == 128u * target - 1u) g_flag = target;
        }
        if (s + 1 < SEQ) {
            const float* Pg = g_P + (size_t)(s + 1) * PSTEP;
            #pragma unroll
            for (int i = 0; i < 4; ++i) {
                int qg = (pq[i] >> 3) * HID + ct * 8 + (pq[i] & 7);
                cp16(sb + SM_P + pq[i] * 512 + ps[i] * 16, Pg + (size_t)qg * BATCH + ps[i] * 4);
            }
            CP_COMMIT();
        }
        if (tid == 0) {
            while (g_flag < target) { }
            __threadfence();
        }
        __syncthreads();
    }
}

// ---------------- classifier ----------------
__global__ void out_kernel(const float* __restrict__ W_out,
                           const float* __restrict__ b_out,
                           float* __restrict__ out) {
    int c = blockIdx.x, b = blockIdx.y;
    const float* h = g_hfin + (size_t)b * HID;
    float sum = 0.0f;
    for (int d = threadIdx.x; d < HID; d += 128)
        sum += h[d] * W_out[c * HID + d];
    #pragma unroll
    for (int o = 16; o; o >>= 1) sum += __shfl_xor_sync(0xFFFFFFFFu, sum, o);
    __shared__ float red[4];
    if ((threadIdx.x & 31) == 0) red[threadIdx.x >> 5] = sum;
    __syncthreads();
    if (threadIdx.x == 0)
        out[b * NCLS + c] = red[0] + red[1] + red[2] + red[3] + b_out[c];
}

extern "C" void kernel_launch(void* const* d_in, const int* in_sizes, int n_in,
                              void* d_out, int out_size) {
    const float* x     = (const float*)d_in[0];
    const float* h0    = (const float*)d_in[1];
    const float* c0    = (const float*)d_in[2];
    const float* W_ih  = (const float*)d_in[3];
    const float* W_hh  = (const float*)d_in[4];
    const float* b_ih  = (const float*)d_in[5];
    const float* b_hh  = (const float*)d_in[6];
    const float* W_out = (const float*)d_in[7];
    const float* b_out = (const float*)d_in[8];
    float* out = (float*)d_out;

    cudaFuncSetAttribute(xproj_mma, cudaFuncAttributeMaxDynamicSharedMemorySize, XP_SMEM);
    cudaFuncSetAttribute(step_persist, cudaFuncAttributeMaxDynamicSharedMemorySize, STEP_SMEM);

    init_state<<<BATCH * HID / 256, 256>>>(h0);
    cvt_x<<<BATCH * SEQ * INDIM / 256, 256>>>(x);
    split_Wih<<<4096 * INDIM / 256, 256>>>(W_ih);
    xproj_mma<<<dim3(64, SEQ), 256, XP_SMEM>>>(b_ih, b_hh);
    step_persist<<<128, 256, STEP_SMEM>>>(W_hh, c0);
    out_kernel<<<dim3(NCLS, BATCH), 128>>>(W_out, b_out, out);
}